// round 4
// baseline (speedup 1.0000x reference)
#include <cuda_runtime.h>

#define B_  4
#define T_  2048
#define C_  1024
#define NH_ 16
#define D_  64
#define BT_ (B_ * T_)      // 8192
#define C3_ (3 * C_)       // 3072

// Scratch buffers (no allocation allowed) — device globals.
__device__ float g_qkv[BT_ * C3_];   // [8192, 3072]  q|k|v, biases folded, q pre-scaled by 1/sqrt(D)
__device__ float g_y[BT_ * C_];      // [8192, 1024]  attention output, head-major columns

// ---------------- packed f32x2 helpers (sm_103a FFMA2 path) ----------------
typedef unsigned long long u64;

__device__ __forceinline__ u64 pk2(float lo, float hi) {
    u64 r; asm("mov.b64 %0, {%1,%2};" : "=l"(r) : "f"(lo), "f"(hi)); return r;
}
__device__ __forceinline__ void fma2(u64 &c, u64 a, u64 b) {
    asm("fma.rn.f32x2 %0, %1, %2, %0;" : "+l"(c) : "l"(a), "l"(b));
}
__device__ __forceinline__ void mul2(u64 &c, u64 a) {
    asm("mul.rn.f32x2 %0, %0, %1;" : "+l"(c) : "l"(a));
}
__device__ __forceinline__ float2 upk(u64 v) {
    float2 f; asm("mov.b64 {%0,%1}, %2;" : "=f"(f.x), "=f"(f.y) : "l"(v)); return f;
}

// ---------------------------------------------------------------------------
// SGEMM: C[M,N] = A[M,K] @ W[K,N] + epilogue.  BM=BN=128, BK=8, 256 threads,
// 8x8 microtile (2x2 blocks of 4x4), inner product via packed f32x2 FMA.
// MODE 0: qkv epilogue (b_attn; +bQ & *0.125 for q cols; +bK for k cols)
// MODE 1: proj epilogue (b_proj)
// ---------------------------------------------------------------------------
template<int MODE>
__global__ __launch_bounds__(256) void sgemm_kernel(
    const float* __restrict__ A, const float* __restrict__ W,
    const float* __restrict__ bias,
    const float* __restrict__ bQ, const float* __restrict__ bK,
    float* __restrict__ Cout, int M, int N, int K)
{
    __shared__ float As[8][128];   // A tile transposed: As[k][m]
    __shared__ float Bs[8][128];   // B tile natural:    Bs[k][n]

    const int tid = threadIdx.x;
    const int tx = tid & 15, ty = tid >> 4;
    const int crow = blockIdx.y * 128, ccol = blockIdx.x * 128;

    const int arow = tid >> 1, acol = (tid & 1) * 4;   // 128 rows x 8 cols
    const int brow = tid >> 5, bcol = (tid & 31) * 4;  // 8 rows x 128 cols
    const float* Ag = A + (size_t)(crow + arow) * K + acol;
    const float* Wg = W + (size_t)brow * N + (ccol + bcol);

    // accumulators: 8 rows x 4 column-pairs (packed f32x2)
    u64 c2[8][4];
    #pragma unroll
    for (int i = 0; i < 8; i++)
        #pragma unroll
        for (int jp = 0; jp < 4; jp++) c2[i][jp] = 0ull;

    float4 pa = *(const float4*)Ag;
    float4 pb = *(const float4*)Wg;
    const int nk = K >> 3;

    for (int kt = 0; kt < nk; kt++) {
        As[acol + 0][arow] = pa.x;
        As[acol + 1][arow] = pa.y;
        As[acol + 2][arow] = pa.z;
        As[acol + 3][arow] = pa.w;
        *(float4*)&Bs[brow][bcol] = pb;
        __syncthreads();

        if (kt + 1 < nk) {   // register prefetch of next tile
            pa = *(const float4*)(Ag + (kt + 1) * 8);
            pb = *(const float4*)(Wg + (size_t)(kt + 1) * 8 * N);
        }

        #pragma unroll
        for (int k = 0; k < 8; k++) {
            float a[8];
            *(float4*)&a[0] = *(const float4*)&As[k][ty * 4];
            *(float4*)&a[4] = *(const float4*)&As[k][64 + ty * 4];
            u64 b2[4];
            b2[0] = *(const u64*)&Bs[k][tx * 4];
            b2[1] = *(const u64*)&Bs[k][tx * 4 + 2];
            b2[2] = *(const u64*)&Bs[k][64 + tx * 4];
            b2[3] = *(const u64*)&Bs[k][64 + tx * 4 + 2];
            #pragma unroll
            for (int i = 0; i < 8; i++) {
                u64 ad = pk2(a[i], a[i]);
                #pragma unroll
                for (int jp = 0; jp < 4; jp++) fma2(c2[i][jp], ad, b2[jp]);
            }
        }
        __syncthreads();
    }

    // epilogue
    #pragma unroll
    for (int ri = 0; ri < 2; ri++)
    #pragma unroll
    for (int ii = 0; ii < 4; ii++) {
        const int i = ri * 4 + ii;
        const int r = crow + ri * 64 + ty * 4 + ii;
        #pragma unroll
        for (int ci = 0; ci < 2; ci++) {
            const int n0 = ccol + ci * 64 + tx * 4;
            float2 p0 = upk(c2[i][ci * 2 + 0]);
            float2 p1 = upk(c2[i][ci * 2 + 1]);
            float v[4] = { p0.x, p0.y, p1.x, p1.y };
            #pragma unroll
            for (int j = 0; j < 4; j++) v[j] += bias[n0 + j];
            if (MODE == 0) {
                if (n0 < C_) {
                    #pragma unroll
                    for (int j = 0; j < 4; j++) v[j] = (v[j] + bQ[n0 + j]) * 0.125f; // fold 1/sqrt(64)
                } else if (n0 < 2 * C_) {
                    #pragma unroll
                    for (int j = 0; j < 4; j++) v[j] = v[j] + bK[n0 - C_ + j];
                }
            }
            *(float4*)&Cout[(size_t)r * N + n0] = make_float4(v[0], v[1], v[2], v[3]);
        }
    }
}

// ---------------------------------------------------------------------------
// Flash attention (fp32, packed f32x2 FMA). One CTA = (b, h, 64-row q tile).
// Bq=Bk=64, D=64. 256 threads as 16(ty) x 16(tx), 4x4 microtiles.
// Smem: Qs natural [i][d]; KP holds K transposed+swizzled [d][j] then reused
// for P [i][j]; Vs natural [k][d].  48 KB static.
// ---------------------------------------------------------------------------
__global__ __launch_bounds__(256) void attn_kernel()
{
    __shared__ float Qs[64 * 64];
    __shared__ float KP[64 * 64];
    __shared__ float Vs[64 * 64];

    const int tid = threadIdx.x;
    const int tx = tid & 15, ty = tid >> 4;
    const int qt = blockIdx.x, h = blockIdx.y, b = blockIdx.z;
    const int q0 = qt * 64;
    const size_t rowbase = (size_t)b * T_ * C3_ + (size_t)h * D_;

    // Load Q tile (bQ added + 1/sqrt(D) folded during GEMM epilogue)
    #pragma unroll
    for (int r = 0; r < 4; r++) {
        int cidx = tid + 256 * r;
        int i = cidx >> 4, f = cidx & 15;
        *(float4*)&Qs[i * 64 + f * 4] =
            *(const float4*)&g_qkv[rowbase + (size_t)(q0 + i) * C3_ + f * 4];
    }

    const float NEG = -1e30f;
    float m[4], l[4];
    u64 o2[4][2];
    #pragma unroll
    for (int ii = 0; ii < 4; ii++) {
        m[ii] = NEG; l[ii] = 0.f;
        o2[ii][0] = 0ull; o2[ii][1] = 0ull;
    }

    for (int kt = 0; kt <= qt; kt++) {
        const int k0 = kt * 64;
        __syncthreads();  // previous iteration's KP/Vs readers done (covers Qs store->read too)

        // Load K (transposed + XOR swizzle) and V (natural)
        #pragma unroll
        for (int r = 0; r < 4; r++) {
            int cidx = tid + 256 * r;
            int j = cidx >> 4, f = cidx & 15;
            size_t gro = rowbase + (size_t)(k0 + j) * C3_;
            float4 kv = *(const float4*)&g_qkv[gro + C_ + f * 4];
            int pcol = (((j >> 2) ^ f) << 2) + (j & 3);
            KP[(4 * f + 0) * 64 + pcol] = kv.x;
            KP[(4 * f + 1) * 64 + pcol] = kv.y;
            KP[(4 * f + 2) * 64 + pcol] = kv.z;
            KP[(4 * f + 3) * 64 + pcol] = kv.w;
            *(float4*)&Vs[j * 64 + f * 4] =
                *(const float4*)&g_qkv[gro + 2 * C_ + f * 4];
        }
        __syncthreads();

        // S = Q K^T   (packed pairs along k-columns)
        u64 s2[4][2];
        #pragma unroll
        for (int ii = 0; ii < 4; ii++) { s2[ii][0] = 0ull; s2[ii][1] = 0ull; }

        #pragma unroll 8
        for (int d = 0; d < 64; d++) {
            float a0 = Qs[(ty * 4 + 0) * 64 + d];
            float a1 = Qs[(ty * 4 + 1) * 64 + d];
            float a2 = Qs[(ty * 4 + 2) * 64 + d];
            float a3 = Qs[(ty * 4 + 3) * 64 + d];
            const int sw = d * 64 + ((tx ^ (d >> 2)) << 2);
            u64 b0 = *(const u64*)&KP[sw];
            u64 b1 = *(const u64*)&KP[sw + 2];
            u64 ad;
            ad = pk2(a0, a0); fma2(s2[0][0], ad, b0); fma2(s2[0][1], ad, b1);
            ad = pk2(a1, a1); fma2(s2[1][0], ad, b0); fma2(s2[1][1], ad, b1);
            ad = pk2(a2, a2); fma2(s2[2][0], ad, b0); fma2(s2[2][1], ad, b1);
            ad = pk2(a3, a3); fma2(s2[3][0], ad, b0); fma2(s2[3][1], ad, b1);
        }

        float s[4][4];
        #pragma unroll
        for (int ii = 0; ii < 4; ii++) {
            float2 p0 = upk(s2[ii][0]), p1 = upk(s2[ii][1]);
            s[ii][0] = p0.x; s[ii][1] = p0.y; s[ii][2] = p1.x; s[ii][3] = p1.y;
        }

        if (kt == qt) {  // diagonal tile: causal mask
            #pragma unroll
            for (int ii = 0; ii < 4; ii++)
                #pragma unroll
                for (int j = 0; j < 4; j++)
                    if (tx * 4 + j > ty * 4 + ii) s[ii][j] = NEG;
        }

        // online softmax (row reductions across 16 tx lanes)
        #pragma unroll
        for (int ii = 0; ii < 4; ii++) {
            float mt = fmaxf(fmaxf(s[ii][0], s[ii][1]), fmaxf(s[ii][2], s[ii][3]));
            mt = fmaxf(mt, __shfl_xor_sync(0xffffffffu, mt, 1));
            mt = fmaxf(mt, __shfl_xor_sync(0xffffffffu, mt, 2));
            mt = fmaxf(mt, __shfl_xor_sync(0xffffffffu, mt, 4));
            mt = fmaxf(mt, __shfl_xor_sync(0xffffffffu, mt, 8));
            float mnew = fmaxf(m[ii], mt);
            float alpha = __expf(m[ii] - mnew);
            float sum = 0.f;
            #pragma unroll
            for (int j = 0; j < 4; j++) {
                s[ii][j] = __expf(s[ii][j] - mnew);
                sum += s[ii][j];
            }
            sum += __shfl_xor_sync(0xffffffffu, sum, 1);
            sum += __shfl_xor_sync(0xffffffffu, sum, 2);
            sum += __shfl_xor_sync(0xffffffffu, sum, 4);
            sum += __shfl_xor_sync(0xffffffffu, sum, 8);
            l[ii] = l[ii] * alpha + sum;
            m[ii] = mnew;
            u64 ad = pk2(alpha, alpha);
            mul2(o2[ii][0], ad);
            mul2(o2[ii][1], ad);
        }

        __syncthreads();   // all reads of KP done -> safe to overwrite with P
        #pragma unroll
        for (int ii = 0; ii < 4; ii++)
            *(float4*)&KP[(ty * 4 + ii) * 64 + tx * 4] =
                make_float4(s[ii][0], s[ii][1], s[ii][2], s[ii][3]);
        __syncthreads();

        // O += P @ V  (packed pairs along d-columns)
        #pragma unroll 8
        for (int k = 0; k < 64; k++) {
            float a0 = KP[(ty * 4 + 0) * 64 + k];
            float a1 = KP[(ty * 4 + 1) * 64 + k];
            float a2 = KP[(ty * 4 + 2) * 64 + k];
            float a3 = KP[(ty * 4 + 3) * 64 + k];
            u64 b0 = *(const u64*)&Vs[k * 64 + tx * 4];
            u64 b1 = *(const u64*)&Vs[k * 64 + tx * 4 + 2];
            u64 ad;
            ad = pk2(a0, a0); fma2(o2[0][0], ad, b0); fma2(o2[0][1], ad, b1);
            ad = pk2(a1, a1); fma2(o2[1][0], ad, b0); fma2(o2[1][1], ad, b1);
            ad = pk2(a2, a2); fma2(o2[2][0], ad, b0); fma2(o2[2][1], ad, b1);
            ad = pk2(a3, a3); fma2(o2[3][0], ad, b0); fma2(o2[3][1], ad, b1);
        }
    }

    // normalize and write y in [b, t, h, d] layout (columns h*D + d)
    #pragma unroll
    for (int ii = 0; ii < 4; ii++) {
        float inv = 1.f / l[ii];
        float2 p0 = upk(o2[ii][0]), p1 = upk(o2[ii][1]);
        *(float4*)&g_y[(size_t)(b * T_ + q0 + ty * 4 + ii) * C_ + h * D_ + tx * 4] =
            make_float4(p0.x * inv, p0.y * inv, p1.x * inv, p1.y * inv);
    }
}

// ---------------------------------------------------------------------------
extern "C" void kernel_launch(void* const* d_in, const int* in_sizes, int n_in,
                              void* d_out, int out_size)
{
    const float* x      = (const float*)d_in[0];
    const float* W_attn = (const float*)d_in[1];
    const float* b_attn = (const float*)d_in[2];
    const float* bQ     = (const float*)d_in[3];
    const float* bK     = (const float*)d_in[4];
    const float* W_proj = (const float*)d_in[5];
    const float* b_proj = (const float*)d_in[6];
    float* out = (float*)d_out;

    float *qkv_p = nullptr, *y_p = nullptr;
    cudaGetSymbolAddress((void**)&qkv_p, g_qkv);
    cudaGetSymbolAddress((void**)&y_p, g_y);

    // 1) qkv = x @ W_attn + b_attn (+bQ,*0.125 | +bK)        [8192, 3072]
    sgemm_kernel<0><<<dim3(C3_ / 128, BT_ / 128), 256>>>(
        x, W_attn, b_attn, bQ, bK, qkv_p, BT_, C3_, C_);

    // 2) flash attention -> g_y                              [8192, 1024]
    attn_kernel<<<dim3(T_ / 64, NH_, B_), 256>>>();

    // 3) out = y @ W_proj + b_proj                           [8192, 1024]
    sgemm_kernel<1><<<dim3(C_ / 128, BT_ / 128), 256>>>(
        y_p, W_proj, b_proj, nullptr, nullptr, out, BT_, C_, C_);
}

// round 5
// speedup vs baseline: 1.3172x; 1.3172x over previous
#include <cuda_runtime.h>

#define B_  4
#define T_  2048
#define C_  1024
#define NH_ 16
#define D_  64
#define BT_ (B_ * T_)      // 8192
#define C3_ (3 * C_)       // 3072

__device__ float g_qkv[(size_t)BT_ * C3_];   // q|k|v, biases folded, q scaled 1/8
__device__ float g_y[(size_t)BT_ * C_];      // attention out, head-major cols

// ---------------- tf32 helpers ----------------
__device__ __forceinline__ unsigned hitf(float x) {
    unsigned r; asm("cvt.rna.tf32.f32 %0, %1;" : "=r"(r) : "f"(x)); return r;
}
__device__ __forceinline__ void split1(float x, unsigned &h, unsigned &l) {
    h = hitf(x); l = hitf(x - __uint_as_float(h));
}
__device__ __forceinline__ void split4(float4 v, uint4 &h, uint4 &l) {
    split1(v.x, h.x, l.x); split1(v.y, h.y, l.y);
    split1(v.z, h.z, l.z); split1(v.w, h.w, l.w);
}
__device__ __forceinline__ void mma8(float c[4], const unsigned a[4], const unsigned b[2]) {
    asm("mma.sync.aligned.m16n8k8.row.col.f32.tf32.tf32.f32 "
        "{%0,%1,%2,%3}, {%4,%5,%6,%7}, {%8,%9}, {%0,%1,%2,%3};"
        : "+f"(c[0]), "+f"(c[1]), "+f"(c[2]), "+f"(c[3])
        : "r"(a[0]), "r"(a[1]), "r"(a[2]), "r"(a[3]), "r"(b[0]), "r"(b[1]));
}

// ---------------------------------------------------------------------------
// tf32x3 GEMM: C[M,N] = A[M,K] @ W[K,N] + epilogue. BM=BN=128, BK=16, 8 warps.
// A smem [m][k] stride 20 (hi/lo), B smem [k][n] stride 136 (hi/lo).
// MODE 0: qkv epilogue.  MODE 1: +b_proj.
// ---------------------------------------------------------------------------
template<int MODE>
__global__ __launch_bounds__(256) void gemm_tf32(
    const float* __restrict__ A, const float* __restrict__ W,
    const float* __restrict__ bias, const float* __restrict__ bQ,
    const float* __restrict__ bK, float* __restrict__ Cout,
    int M, int N, int K)
{
    __shared__ unsigned Ah[128 * 20], Al[128 * 20];
    __shared__ unsigned Bh[16 * 136], Bl[16 * 136];

    const int tid = threadIdx.x, lane = tid & 31, warp = tid >> 5;
    const int g = lane >> 2, c = lane & 3;
    const int wm = warp >> 2, wn = warp & 3;
    const int crow = blockIdx.y * 128, ccol = blockIdx.x * 128;

    float acc[4][4][4];
    #pragma unroll
    for (int i = 0; i < 4; i++)
        #pragma unroll
        for (int j = 0; j < 4; j++)
            #pragma unroll
            for (int f = 0; f < 4; f++) acc[i][j][f] = 0.f;

    // loader geometry: 2 float4 per matrix per thread
    int arow[2], akq[2], bk[2], bn4[2];
    #pragma unroll
    for (int q = 0; q < 2; q++) {
        int idx = tid + 256 * q;
        arow[q] = idx >> 2;  akq[q] = (idx & 3) * 4;     // A: 128 rows x 16
        bk[q]   = idx >> 5;  bn4[q] = (idx & 31) * 4;    // B: 16 rows x 128
    }

    const int nk = K >> 4;
    float4 pa[2], pb[2];
    #pragma unroll
    for (int q = 0; q < 2; q++) {
        pa[q] = *(const float4*)&A[(size_t)(crow + arow[q]) * K + akq[q]];
        pb[q] = *(const float4*)&W[(size_t)bk[q] * N + ccol + bn4[q]];
    }

    for (int kt = 0; kt < nk; kt++) {
        #pragma unroll
        for (int q = 0; q < 2; q++) {
            uint4 h, l;
            split4(pa[q], h, l);
            *(uint4*)&Ah[arow[q] * 20 + akq[q]] = h;
            *(uint4*)&Al[arow[q] * 20 + akq[q]] = l;
            split4(pb[q], h, l);
            *(uint4*)&Bh[bk[q] * 136 + bn4[q]] = h;
            *(uint4*)&Bl[bk[q] * 136 + bn4[q]] = l;
        }
        __syncthreads();

        if (kt + 1 < nk) {
            #pragma unroll
            for (int q = 0; q < 2; q++) {
                pa[q] = *(const float4*)&A[(size_t)(crow + arow[q]) * K + (kt + 1) * 16 + akq[q]];
                pb[q] = *(const float4*)&W[(size_t)((kt + 1) * 16 + bk[q]) * N + ccol + bn4[q]];
            }
        }

        #pragma unroll
        for (int ks = 0; ks < 2; ks++) {
            unsigned bh[4][2], bl[4][2];
            #pragma unroll
            for (int nt = 0; nt < 4; nt++) {
                int bb = (ks * 8 + c) * 136 + wn * 32 + nt * 8 + g;
                bh[nt][0] = Bh[bb];       bh[nt][1] = Bh[bb + 544];   // k+4 -> +4*136
                bl[nt][0] = Bl[bb];       bl[nt][1] = Bl[bb + 544];
            }
            #pragma unroll
            for (int mt = 0; mt < 4; mt++) {
                int ab = (wm * 64 + mt * 16 + g) * 20 + ks * 8 + c;
                unsigned ah[4] = { Ah[ab], Ah[ab + 160], Ah[ab + 4], Ah[ab + 164] };
                unsigned al[4] = { Al[ab], Al[ab + 160], Al[ab + 4], Al[ab + 164] };
                #pragma unroll
                for (int nt = 0; nt < 4; nt++) {
                    mma8(acc[mt][nt], ah, bh[nt]);
                    mma8(acc[mt][nt], ah, bl[nt]);
                    mma8(acc[mt][nt], al, bh[nt]);
                }
            }
        }
        __syncthreads();
    }

    // epilogue: C-frag (g,2c),(g,2c+1),(g+8,2c),(g+8,2c+1)
    #pragma unroll
    for (int mt = 0; mt < 4; mt++)
    #pragma unroll
    for (int hh = 0; hh < 2; hh++) {
        int row = crow + wm * 64 + mt * 16 + g + 8 * hh;
        #pragma unroll
        for (int nt = 0; nt < 4; nt++) {
            int n0 = ccol + wn * 32 + nt * 8 + 2 * c;
            float v0 = acc[mt][nt][2 * hh]     + bias[n0];
            float v1 = acc[mt][nt][2 * hh + 1] + bias[n0 + 1];
            if (MODE == 0) {
                if (n0 < C_)          { v0 = (v0 + bQ[n0]) * 0.125f; v1 = (v1 + bQ[n0 + 1]) * 0.125f; }
                else if (n0 < 2 * C_) { v0 += bK[n0 - C_];           v1 += bK[n0 + 1 - C_]; }
            }
            *(float2*)&Cout[(size_t)row * N + n0] = make_float2(v0, v1);
        }
    }
}

// ---------------------------------------------------------------------------
// Flash attention, tf32 mma. CTA = 128 q-rows x (h, b); 8 warps, 16 rows each.
// S: 3-mma split (Qh/Ql x Kh/Kl). P@V: Phi x (Vh + Vl) (2 mma).
// Dynamic smem 176128 B.
// ---------------------------------------------------------------------------
#define AQH 0
#define AQL 8704            // 128*68
#define AKH 17408
#define AKL 21760           // +64*68
#define AVH 26112
#define AVL 30720           // +64*72
#define APS 35328           // 8*16*68
#define ASMEM_WORDS 44032   // *4 = 176128 B

__global__ __launch_bounds__(256) void attn_tf32()
{
    extern __shared__ unsigned sm[];
    unsigned *QH = sm + AQH, *QL = sm + AQL;
    unsigned *KH = sm + AKH, *KL = sm + AKL;
    unsigned *VH = sm + AVH, *VL = sm + AVL;
    unsigned *PS = sm + APS;

    const int tid = threadIdx.x, lane = tid & 31, w = tid >> 5;
    const int g = lane >> 2, c = lane & 3;
    const int qt = blockIdx.x, h = blockIdx.y, b = blockIdx.z;
    const int q0 = qt * 128;
    const size_t rb = (size_t)b * T_ * C3_ + (size_t)h * D_;

    // Q fill (hi/lo), natural [q][d] stride 68
    #pragma unroll
    for (int r = 0; r < 8; r++) {
        int idx = tid + 256 * r;
        int qq = idx >> 4, d0 = (idx & 15) * 4;
        float4 v = *(const float4*)&g_qkv[rb + (size_t)(q0 + qq) * C3_ + d0];
        uint4 hh, ll; split4(v, hh, ll);
        *(uint4*)&QH[qq * 68 + d0] = hh;
        *(uint4*)&QL[qq * 68 + d0] = ll;
    }

    float m0 = -1e30f, m1 = -1e30f, l0 = 0.f, l1 = 0.f;
    float o[8][4];
    #pragma unroll
    for (int nt = 0; nt < 8; nt++)
        #pragma unroll
        for (int f = 0; f < 4; f++) o[nt][f] = 0.f;

    const int row0 = q0 + w * 16 + g, row1 = row0 + 8;
    const int nkt = 2 * qt + 2;

    for (int kt = 0; kt < nkt; kt++) {
        __syncthreads();   // prior iteration readers of K/V done (covers Q fill on iter 0)
        #pragma unroll
        for (int r = 0; r < 4; r++) {
            int idx = tid + 256 * r;
            int kc = idx >> 4, d0 = (idx & 15) * 4;
            size_t go = rb + (size_t)(kt * 64 + kc) * C3_;
            uint4 hh, ll;
            split4(*(const float4*)&g_qkv[go + C_ + d0], hh, ll);
            *(uint4*)&KH[kc * 68 + d0] = hh;  *(uint4*)&KL[kc * 68 + d0] = ll;
            split4(*(const float4*)&g_qkv[go + 2 * C_ + d0], hh, ll);
            *(uint4*)&VH[kc * 72 + d0] = hh;  *(uint4*)&VL[kc * 72 + d0] = ll;
        }
        __syncthreads();

        // ---- S = Q K^T (3-mma split) ----
        float s[8][4];
        #pragma unroll
        for (int nt = 0; nt < 8; nt++)
            #pragma unroll
            for (int f = 0; f < 4; f++) s[nt][f] = 0.f;

        #pragma unroll
        for (int ks = 0; ks < 8; ks++) {
            int qb = (w * 16 + g) * 68 + ks * 8 + c;
            unsigned qh[4] = { QH[qb], QH[qb + 544], QH[qb + 4], QH[qb + 548] };
            unsigned ql[4] = { QL[qb], QL[qb + 544], QL[qb + 4], QL[qb + 548] };
            #pragma unroll
            for (int nt = 0; nt < 8; nt++) {
                int kb = (nt * 8 + g) * 68 + ks * 8 + c;
                unsigned bh[2] = { KH[kb], KH[kb + 4] };
                unsigned bl[2] = { KL[kb], KL[kb + 4] };
                mma8(s[nt], qh, bh);
                mma8(s[nt], qh, bl);
                mma8(s[nt], ql, bh);
            }
        }

        if (kt >= 2 * qt) {   // only the last two tiles touch the diagonal
            #pragma unroll
            for (int nt = 0; nt < 8; nt++) {
                int col = kt * 64 + nt * 8 + 2 * c;
                if (col     > row0) s[nt][0] = -1e30f;
                if (col + 1 > row0) s[nt][1] = -1e30f;
                if (col     > row1) s[nt][2] = -1e30f;
                if (col + 1 > row1) s[nt][3] = -1e30f;
            }
        }

        // ---- online softmax (rows g and g+8; reduce over 4 c-lanes) ----
        float mx0 = -1e30f, mx1 = -1e30f;
        #pragma unroll
        for (int nt = 0; nt < 8; nt++) {
            mx0 = fmaxf(mx0, fmaxf(s[nt][0], s[nt][1]));
            mx1 = fmaxf(mx1, fmaxf(s[nt][2], s[nt][3]));
        }
        mx0 = fmaxf(mx0, __shfl_xor_sync(0xffffffffu, mx0, 1));
        mx0 = fmaxf(mx0, __shfl_xor_sync(0xffffffffu, mx0, 2));
        mx1 = fmaxf(mx1, __shfl_xor_sync(0xffffffffu, mx1, 1));
        mx1 = fmaxf(mx1, __shfl_xor_sync(0xffffffffu, mx1, 2));
        float mn0 = fmaxf(m0, mx0), mn1 = fmaxf(m1, mx1);
        float a0 = __expf(m0 - mn0), a1 = __expf(m1 - mn1);
        float sum0 = 0.f, sum1 = 0.f;
        #pragma unroll
        for (int nt = 0; nt < 8; nt++) {
            s[nt][0] = __expf(s[nt][0] - mn0);
            s[nt][1] = __expf(s[nt][1] - mn0);
            s[nt][2] = __expf(s[nt][2] - mn1);
            s[nt][3] = __expf(s[nt][3] - mn1);
            sum0 += s[nt][0] + s[nt][1];
            sum1 += s[nt][2] + s[nt][3];
        }
        sum0 += __shfl_xor_sync(0xffffffffu, sum0, 1);
        sum0 += __shfl_xor_sync(0xffffffffu, sum0, 2);
        sum1 += __shfl_xor_sync(0xffffffffu, sum1, 1);
        sum1 += __shfl_xor_sync(0xffffffffu, sum1, 2);
        l0 = l0 * a0 + sum0;  m0 = mn0;
        l1 = l1 * a1 + sum1;  m1 = mn1;
        #pragma unroll
        for (int nt = 0; nt < 8; nt++) {
            o[nt][0] *= a0; o[nt][1] *= a0;
            o[nt][2] *= a1; o[nt][3] *= a1;
        }

        // ---- P (hi) -> per-warp smem, then O += P V (2-mma split) ----
        #pragma unroll
        for (int nt = 0; nt < 8; nt++) {
            int pw = w * 1088 + g * 68 + nt * 8 + 2 * c;
            *(uint2*)&PS[pw]       = make_uint2(hitf(s[nt][0]), hitf(s[nt][1]));
            *(uint2*)&PS[pw + 544] = make_uint2(hitf(s[nt][2]), hitf(s[nt][3]));
        }
        __syncwarp();

        #pragma unroll
        for (int ks = 0; ks < 8; ks++) {
            int pb = w * 1088 + g * 68 + ks * 8 + c;
            unsigned pa[4] = { PS[pb], PS[pb + 544], PS[pb + 4], PS[pb + 548] };
            #pragma unroll
            for (int nt = 0; nt < 8; nt++) {
                int vb = (ks * 8 + c) * 72 + nt * 8 + g;
                unsigned bh[2] = { VH[vb], VH[vb + 288] };   // k+4 -> +4*72
                unsigned bl[2] = { VL[vb], VL[vb + 288] };
                mma8(o[nt], pa, bh);
                mma8(o[nt], pa, bl);
            }
        }
    }

    // normalize + write y [b*T+row][h*64 + d]
    float i0 = 1.f / l0, i1 = 1.f / l1;
    #pragma unroll
    for (int nt = 0; nt < 8; nt++) {
        int col = h * D_ + nt * 8 + 2 * c;
        *(float2*)&g_y[(size_t)(b * T_ + row0) * C_ + col] =
            make_float2(o[nt][0] * i0, o[nt][1] * i0);
        *(float2*)&g_y[(size_t)(b * T_ + row1) * C_ + col] =
            make_float2(o[nt][2] * i1, o[nt][3] * i1);
    }
}

// ---------------------------------------------------------------------------
extern "C" void kernel_launch(void* const* d_in, const int* in_sizes, int n_in,
                              void* d_out, int out_size)
{
    const float* x      = (const float*)d_in[0];
    const float* W_attn = (const float*)d_in[1];
    const float* b_attn = (const float*)d_in[2];
    const float* bQ     = (const float*)d_in[3];
    const float* bK     = (const float*)d_in[4];
    const float* W_proj = (const float*)d_in[5];
    const float* b_proj = (const float*)d_in[6];
    float* out = (float*)d_out;

    float *qkv_p = nullptr, *y_p = nullptr;
    cudaGetSymbolAddress((void**)&qkv_p, g_qkv);
    cudaGetSymbolAddress((void**)&y_p, g_y);

    cudaFuncSetAttribute(attn_tf32, cudaFuncAttributeMaxDynamicSharedMemorySize,
                         ASMEM_WORDS * 4);

    gemm_tf32<0><<<dim3(C3_ / 128, BT_ / 128), 256>>>(
        x, W_attn, b_attn, bQ, bK, qkv_p, BT_, C3_, C_);

    attn_tf32<<<dim3(T_ / 128, NH_, B_), 256, ASMEM_WORDS * 4>>>();

    gemm_tf32<1><<<dim3(C_ / 128, BT_ / 128), 256>>>(
        y_p, W_proj, b_proj, nullptr, nullptr, out, BT_, C_, C_);
}

// round 7
// speedup vs baseline: 2.0106x; 1.5264x over previous
#include <cuda_runtime.h>
#include <cuda_bf16.h>

#define B_  4
#define T_  2048
#define C_  1024
#define NH_ 16
#define D_  64
#define BT_ (B_ * T_)      // 8192
#define C3_ (3 * C_)       // 3072

__device__ float g_qkv[(size_t)BT_ * C3_];   // q|k|v, biases folded, q scaled 1/8
__device__ float g_y[(size_t)BT_ * C_];      // attention out, head-major cols

// ---------------- bf16 helpers ----------------
__device__ __forceinline__ void split4bf(float4 v, uint2 &h, uint2 &l) {
    float e[4] = { v.x, v.y, v.z, v.w };
    unsigned hs[4], ls[4];
    #pragma unroll
    for (int i = 0; i < 4; i++) {
        __nv_bfloat16 bh = __float2bfloat16(e[i]);
        hs[i] = __bfloat16_as_ushort(bh);
        ls[i] = __bfloat16_as_ushort(__float2bfloat16(e[i] - __bfloat162float(bh)));
    }
    h.x = hs[0] | (hs[1] << 16);  h.y = hs[2] | (hs[3] << 16);
    l.x = ls[0] | (ls[1] << 16);  l.y = ls[2] | (ls[3] << 16);
}
__device__ __forceinline__ unsigned pk2bf(float a, float b) {   // a -> low half
    return __bfloat16_as_ushort(__float2bfloat16(a)) |
           ((unsigned)__bfloat16_as_ushort(__float2bfloat16(b)) << 16);
}
__device__ __forceinline__ float bflo(float x) {               // residual after bf16 round
    return x - __bfloat162float(__float2bfloat16(x));
}
__device__ __forceinline__ void mmabf(float c[4], const unsigned a[4], const unsigned b[2]) {
    asm("mma.sync.aligned.m16n8k16.row.col.f32.bf16.bf16.f32 "
        "{%0,%1,%2,%3}, {%4,%5,%6,%7}, {%8,%9}, {%0,%1,%2,%3};"
        : "+f"(c[0]), "+f"(c[1]), "+f"(c[2]), "+f"(c[3])
        : "r"(a[0]), "r"(a[1]), "r"(a[2]), "r"(a[3]), "r"(b[0]), "r"(b[1]));
}
__device__ __forceinline__ void ldsm4(unsigned r[4], unsigned a) {
    asm volatile("ldmatrix.sync.aligned.m8n8.x4.shared.b16 {%0,%1,%2,%3}, [%4];"
        : "=r"(r[0]), "=r"(r[1]), "=r"(r[2]), "=r"(r[3]) : "r"(a));
}
__device__ __forceinline__ void ldsm4t(unsigned r[4], unsigned a) {
    asm volatile("ldmatrix.sync.aligned.m8n8.x4.trans.shared.b16 {%0,%1,%2,%3}, [%4];"
        : "=r"(r[0]), "=r"(r[1]), "=r"(r[2]), "=r"(r[3]) : "r"(a));
}
__device__ __forceinline__ unsigned sptr(const void* p) {
    return (unsigned)__cvta_generic_to_shared(p);
}

// ---------------------------------------------------------------------------
// bf16x3 GEMM: C = A@W + epilogue. BM=BN=128, BK=32, 8 warps (2x4), warp 64x32.
// A smem [128][40] bf16 (hi/lo), B smem [32][136] bf16 (hi/lo).
// Fragments via ldmatrix (A natural, B trans). MODE 0: qkv epi. MODE 1: +b_proj.
// ---------------------------------------------------------------------------
template<int MODE>
__global__ __launch_bounds__(256) void gemm_bf16(
    const float* __restrict__ A, const float* __restrict__ W,
    const float* __restrict__ bias, const float* __restrict__ bQ,
    const float* __restrict__ bK, float* __restrict__ Cout,
    int M, int N, int K)
{
    __shared__ __align__(16) unsigned short AH[128 * 40], AL[128 * 40];
    __shared__ __align__(16) unsigned short BH[32 * 136], BL[32 * 136];

    const int tid = threadIdx.x, lane = tid & 31, warp = tid >> 5;
    const int g = lane >> 2, c = lane & 3;
    const int wm = warp >> 2, wn = warp & 3;
    const int crow = blockIdx.y * 128, ccol = blockIdx.x * 128;

    float acc[4][4][4];
    #pragma unroll
    for (int i = 0; i < 4; i++)
        #pragma unroll
        for (int j = 0; j < 4; j++)
            #pragma unroll
            for (int f = 0; f < 4; f++) acc[i][j][f] = 0.f;

    int arow[4], akq[4], bk[4], bn4[4];
    #pragma unroll
    for (int q = 0; q < 4; q++) {
        int idx = tid + 256 * q;
        arow[q] = idx >> 3;  akq[q] = (idx & 7) * 4;   // A: 128 x 32
        bk[q]   = idx >> 5;  bn4[q] = (idx & 31) * 4;  // B: 32 x 128
    }

    // ldmatrix lane addresses (byte offsets)
    const int rowA = wm * 64 + (lane & 7) + ((lane >> 3) & 1) * 8;
    const unsigned aOff = (rowA * 40 + ((lane >> 4) & 1) * 8) * 2;
    const int rowB = (lane & 7) + ((lane >> 3) & 1) * 8;
    const int colB = wn * 32 + ((lane >> 4) & 1) * 8;
    const unsigned bOff = (rowB * 136 + colB) * 2;
    const unsigned aAH = sptr(AH) + aOff, aAL = sptr(AL) + aOff;
    const unsigned aBH = sptr(BH) + bOff, aBL = sptr(BL) + bOff;

    const int nk = K >> 5;
    float4 pa[4], pb[4];
    #pragma unroll
    for (int q = 0; q < 4; q++) {
        pa[q] = *(const float4*)&A[(size_t)(crow + arow[q]) * K + akq[q]];
        pb[q] = *(const float4*)&W[(size_t)bk[q] * N + ccol + bn4[q]];
    }

    for (int kt = 0; kt < nk; kt++) {
        #pragma unroll
        for (int q = 0; q < 4; q++) {
            uint2 h, l;
            split4bf(pa[q], h, l);
            *(uint2*)&AH[arow[q] * 40 + akq[q]] = h;
            *(uint2*)&AL[arow[q] * 40 + akq[q]] = l;
            split4bf(pb[q], h, l);
            *(uint2*)&BH[bk[q] * 136 + bn4[q]] = h;
            *(uint2*)&BL[bk[q] * 136 + bn4[q]] = l;
        }
        __syncthreads();

        if (kt + 1 < nk) {
            #pragma unroll
            for (int q = 0; q < 4; q++) {
                pa[q] = *(const float4*)&A[(size_t)(crow + arow[q]) * K + (kt + 1) * 32 + akq[q]];
                pb[q] = *(const float4*)&W[(size_t)((kt + 1) * 32 + bk[q]) * N + ccol + bn4[q]];
            }
        }

        #pragma unroll
        for (int ks = 0; ks < 2; ks++) {
            unsigned bh[4][2], bl[4][2];
            #pragma unroll
            for (int ntp = 0; ntp < 2; ntp++) {
                unsigned off = (ks * 16 * 136 + ntp * 16) * 2;
                unsigned t[4];
                ldsm4t(t, aBH + off);
                bh[2 * ntp][0] = t[0]; bh[2 * ntp][1] = t[1];
                bh[2 * ntp + 1][0] = t[2]; bh[2 * ntp + 1][1] = t[3];
                ldsm4t(t, aBL + off);
                bl[2 * ntp][0] = t[0]; bl[2 * ntp][1] = t[1];
                bl[2 * ntp + 1][0] = t[2]; bl[2 * ntp + 1][1] = t[3];
            }
            #pragma unroll
            for (int mt = 0; mt < 4; mt++) {
                unsigned off = (mt * 16 * 40 + ks * 16) * 2;
                unsigned ah[4], al[4];
                ldsm4(ah, aAH + off);
                ldsm4(al, aAL + off);
                #pragma unroll
                for (int nt = 0; nt < 4; nt++) {
                    mmabf(acc[mt][nt], ah, bh[nt]);
                    mmabf(acc[mt][nt], ah, bl[nt]);
                    mmabf(acc[mt][nt], al, bh[nt]);
                }
            }
        }
        __syncthreads();
    }

    // epilogue: C-frag rows g/g+8, cols 2c,2c+1
    #pragma unroll
    for (int mt = 0; mt < 4; mt++)
    #pragma unroll
    for (int hh = 0; hh < 2; hh++) {
        int row = crow + wm * 64 + mt * 16 + g + 8 * hh;
        #pragma unroll
        for (int nt = 0; nt < 4; nt++) {
            int n0 = ccol + wn * 32 + nt * 8 + 2 * c;
            float v0 = acc[mt][nt][2 * hh]     + bias[n0];
            float v1 = acc[mt][nt][2 * hh + 1] + bias[n0 + 1];
            if (MODE == 0) {
                if (n0 < C_)          { v0 = (v0 + bQ[n0]) * 0.125f; v1 = (v1 + bQ[n0 + 1]) * 0.125f; }
                else if (n0 < 2 * C_) { v0 += bK[n0 - C_];           v1 += bK[n0 + 1 - C_]; }
            }
            *(float2*)&Cout[(size_t)row * N + n0] = make_float2(v0, v1);
        }
    }
}

// ---------------------------------------------------------------------------
// Flash attention, bf16x3 mma + ldmatrix, P in registers.
// CTA = 128 q-rows x (h, b); 8 warps, 16 rows each. Bk=64.
// Smem bf16 stride 72 (144 B rows, conflict-free ldmatrix): QH/QL[128][72],
// KH/KL[64][72] ([kcol][d]), VH/VL[64][72] ([kcol][d]).  73728 B dynamic.
// ---------------------------------------------------------------------------
#define SQH 0
#define SQL (128 * 72)
#define SKH (2 * 128 * 72)
#define SKL (SKH + 64 * 72)
#define SVH (SKH + 2 * 64 * 72)
#define SVL (SVH + 64 * 72)
#define ASMEM_BYTES ((2 * 128 * 72 + 4 * 64 * 72) * 2)

__global__ __launch_bounds__(256) void attn_bf16()
{
    extern __shared__ __align__(16) unsigned short smn[];
    unsigned short *QH = smn + SQH, *QL = smn + SQL;
    unsigned short *KH = smn + SKH, *KL = smn + SKL;
    unsigned short *VH = smn + SVH, *VL = smn + SVL;

    const int tid = threadIdx.x, lane = tid & 31, w = tid >> 5;
    const int g = lane >> 2, c = lane & 3;
    const int qt = blockIdx.x, h = blockIdx.y, b = blockIdx.z;
    const int q0 = qt * 128;
    const size_t rb = (size_t)b * T_ * C3_ + (size_t)h * D_;

    // Q fill (hi/lo)
    #pragma unroll
    for (int r = 0; r < 8; r++) {
        int idx = tid + 256 * r;
        int qq = idx >> 4, d0 = (idx & 15) * 4;
        uint2 hh, ll;
        split4bf(*(const float4*)&g_qkv[rb + (size_t)(q0 + qq) * C3_ + d0], hh, ll);
        *(uint2*)&QH[qq * 72 + d0] = hh;
        *(uint2*)&QL[qq * 72 + d0] = ll;
    }

    // ldmatrix lane addresses
    const int rQ = w * 16 + (lane & 7) + ((lane >> 3) & 1) * 8;
    const unsigned qOff = (rQ * 72 + ((lane >> 4) & 1) * 8) * 2;
    const int rK = (lane & 7) + ((lane >> 4) & 1) * 8;          // n rows (+8 for nt+1)
    const unsigned kOff = (rK * 72 + ((lane >> 3) & 1) * 8) * 2; // k-half in cols
    const int rV = (lane & 7) + ((lane >> 3) & 1) * 8;          // k rows (+8 for k-half)
    const unsigned vOff = (rV * 72 + ((lane >> 4) & 1) * 8) * 2; // n-half in cols
    const unsigned aQH = sptr(QH) + qOff, aQL = sptr(QL) + qOff;
    const unsigned aKH = sptr(KH) + kOff, aKL = sptr(KL) + kOff;
    const unsigned aVH = sptr(VH) + vOff, aVL = sptr(VL) + vOff;

    float m0 = -1e30f, m1 = -1e30f, l0 = 0.f, l1 = 0.f;
    float o[8][4];
    #pragma unroll
    for (int nt = 0; nt < 8; nt++)
        #pragma unroll
        for (int f = 0; f < 4; f++) o[nt][f] = 0.f;

    const int row0 = q0 + w * 16 + g, row1 = row0 + 8;
    const int nkt = 2 * qt + 2;

    for (int kt = 0; kt < nkt; kt++) {
        __syncthreads();   // prior iter's K/V readers done (covers Q fill on iter 0)
        #pragma unroll
        for (int r = 0; r < 4; r++) {
            int idx = tid + 256 * r;
            int kc = idx >> 4, d0 = (idx & 15) * 4;
            size_t go = rb + (size_t)(kt * 64 + kc) * C3_;
            uint2 hh, ll;
            split4bf(*(const float4*)&g_qkv[go + C_ + d0], hh, ll);
            *(uint2*)&KH[kc * 72 + d0] = hh;  *(uint2*)&KL[kc * 72 + d0] = ll;
            split4bf(*(const float4*)&g_qkv[go + 2 * C_ + d0], hh, ll);
            *(uint2*)&VH[kc * 72 + d0] = hh;  *(uint2*)&VL[kc * 72 + d0] = ll;
        }
        __syncthreads();

        // ---- S = Q K^T (3-term bf16 split) ----
        float s[8][4];
        #pragma unroll
        for (int nt = 0; nt < 8; nt++)
            #pragma unroll
            for (int f = 0; f < 4; f++) s[nt][f] = 0.f;

        #pragma unroll
        for (int ks = 0; ks < 4; ks++) {
            unsigned qh[4], ql[4];
            ldsm4(qh, aQH + ks * 32);
            ldsm4(ql, aQL + ks * 32);
            unsigned bh[8][2], bl[8][2];
            #pragma unroll
            for (int ntp = 0; ntp < 4; ntp++) {
                unsigned off = (ntp * 16 * 72 + ks * 16) * 2;
                unsigned t[4];
                ldsm4(t, aKH + off);
                bh[2 * ntp][0] = t[0]; bh[2 * ntp][1] = t[1];
                bh[2 * ntp + 1][0] = t[2]; bh[2 * ntp + 1][1] = t[3];
                ldsm4(t, aKL + off);
                bl[2 * ntp][0] = t[0]; bl[2 * ntp][1] = t[1];
                bl[2 * ntp + 1][0] = t[2]; bl[2 * ntp + 1][1] = t[3];
            }
            #pragma unroll
            for (int nt = 0; nt < 8; nt++) {
                mmabf(s[nt], qh, bh[nt]);
                mmabf(s[nt], qh, bl[nt]);
                mmabf(s[nt], ql, bh[nt]);
            }
        }

        if (kt >= 2 * qt) {   // only last two tiles touch the diagonal
            #pragma unroll
            for (int nt = 0; nt < 8; nt++) {
                int col = kt * 64 + nt * 8 + 2 * c;
                if (col     > row0) s[nt][0] = -1e30f;
                if (col + 1 > row0) s[nt][1] = -1e30f;
                if (col     > row1) s[nt][2] = -1e30f;
                if (col + 1 > row1) s[nt][3] = -1e30f;
            }
        }

        // ---- online softmax ----
        float mx0 = -1e30f, mx1 = -1e30f;
        #pragma unroll
        for (int nt = 0; nt < 8; nt++) {
            mx0 = fmaxf(mx0, fmaxf(s[nt][0], s[nt][1]));
            mx1 = fmaxf(mx1, fmaxf(s[nt][2], s[nt][3]));
        }
        mx0 = fmaxf(mx0, __shfl_xor_sync(0xffffffffu, mx0, 1));
        mx0 = fmaxf(mx0, __shfl_xor_sync(0xffffffffu, mx0, 2));
        mx1 = fmaxf(mx1, __shfl_xor_sync(0xffffffffu, mx1, 1));
        mx1 = fmaxf(mx1, __shfl_xor_sync(0xffffffffu, mx1, 2));
        float mn0 = fmaxf(m0, mx0), mn1 = fmaxf(m1, mx1);
        float a0 = __expf(m0 - mn0), a1 = __expf(m1 - mn1);
        float sum0 = 0.f, sum1 = 0.f;
        #pragma unroll
        for (int nt = 0; nt < 8; nt++) {
            s[nt][0] = __expf(s[nt][0] - mn0);
            s[nt][1] = __expf(s[nt][1] - mn0);
            s[nt][2] = __expf(s[nt][2] - mn1);
            s[nt][3] = __expf(s[nt][3] - mn1);
            sum0 += s[nt][0] + s[nt][1];
            sum1 += s[nt][2] + s[nt][3];
        }
        sum0 += __shfl_xor_sync(0xffffffffu, sum0, 1);
        sum0 += __shfl_xor_sync(0xffffffffu, sum0, 2);
        sum1 += __shfl_xor_sync(0xffffffffu, sum1, 1);
        sum1 += __shfl_xor_sync(0xffffffffu, sum1, 2);
        l0 = l0 * a0 + sum0;  m0 = mn0;
        l1 = l1 * a1 + sum1;  m1 = mn1;
        #pragma unroll
        for (int nt = 0; nt < 8; nt++) {
            o[nt][0] *= a0; o[nt][1] *= a0;
            o[nt][2] *= a1; o[nt][3] *= a1;
        }

        // ---- P in registers: C-frag pair-packs into A-frag (hi + lo) ----
        unsigned ph[8][2], pl[8][2];
        #pragma unroll
        for (int nt = 0; nt < 8; nt++) {
            ph[nt][0] = pk2bf(s[nt][0], s[nt][1]);
            ph[nt][1] = pk2bf(s[nt][2], s[nt][3]);
            pl[nt][0] = pk2bf(bflo(s[nt][0]), bflo(s[nt][1]));
            pl[nt][1] = pk2bf(bflo(s[nt][2]), bflo(s[nt][3]));
        }

        // ---- O += P V (3-term) ----
        #pragma unroll
        for (int ks = 0; ks < 4; ks++) {
            unsigned pah[4] = { ph[2 * ks][0], ph[2 * ks][1], ph[2 * ks + 1][0], ph[2 * ks + 1][1] };
            unsigned pal[4] = { pl[2 * ks][0], pl[2 * ks][1], pl[2 * ks + 1][0], pl[2 * ks + 1][1] };
            unsigned bh[8][2], bl[8][2];
            #pragma unroll
            for (int ntp = 0; ntp < 4; ntp++) {
                unsigned off = (ks * 16 * 72 + ntp * 16) * 2;
                unsigned t[4];
                ldsm4t(t, aVH + off);
                bh[2 * ntp][0] = t[0]; bh[2 * ntp][1] = t[1];
                bh[2 * ntp + 1][0] = t[2]; bh[2 * ntp + 1][1] = t[3];
                ldsm4t(t, aVL + off);
                bl[2 * ntp][0] = t[0]; bl[2 * ntp][1] = t[1];
                bl[2 * ntp + 1][0] = t[2]; bl[2 * ntp + 1][1] = t[3];
            }
            #pragma unroll
            for (int nt = 0; nt < 8; nt++) {
                mmabf(o[nt], pah, bh[nt]);
                mmabf(o[nt], pah, bl[nt]);
                mmabf(o[nt], pal, bh[nt]);
            }
        }
    }

    // normalize + write y [b*T+row][h*64 + d]
    float i0 = 1.f / l0, i1 = 1.f / l1;
    #pragma unroll
    for (int nt = 0; nt < 8; nt++) {
        int col = h * D_ + nt * 8 + 2 * c;
        *(float2*)&g_y[(size_t)(b * T_ + row0) * C_ + col] =
            make_float2(o[nt][0] * i0, o[nt][1] * i0);
        *(float2*)&g_y[(size_t)(b * T_ + row1) * C_ + col] =
            make_float2(o[nt][2] * i1, o[nt][3] * i1);
    }
}

// ---------------------------------------------------------------------------
extern "C" void kernel_launch(void* const* d_in, const int* in_sizes, int n_in,
                              void* d_out, int out_size)
{
    const float* x      = (const float*)d_in[0];
    const float* W_attn = (const float*)d_in[1];
    const float* b_attn = (const float*)d_in[2];
    const float* bQ     = (const float*)d_in[3];
    const float* bK     = (const float*)d_in[4];
    const float* W_proj = (const float*)d_in[5];
    const float* b_proj = (const float*)d_in[6];
    float* out = (float*)d_out;

    float *qkv_p = nullptr, *y_p = nullptr;
    cudaGetSymbolAddress((void**)&qkv_p, g_qkv);
    cudaGetSymbolAddress((void**)&y_p, g_y);

    cudaFuncSetAttribute(attn_bf16, cudaFuncAttributeMaxDynamicSharedMemorySize,
                         ASMEM_BYTES);

    gemm_bf16<0><<<dim3(C3_ / 128, BT_ / 128), 256>>>(
        x, W_attn, b_attn, bQ, bK, qkv_p, BT_, C3_, C_);

    attn_bf16<<<dim3(T_ / 128, NH_, B_), 256, ASMEM_BYTES>>>();

    gemm_bf16<1><<<dim3(C_ / 128, BT_ / 128), 256>>>(
        y_p, W_proj, b_proj, nullptr, nullptr, out, BT_, C_, C_);
}

// round 8
// speedup vs baseline: 2.6021x; 1.2942x over previous
#include <cuda_runtime.h>
#include <cuda_bf16.h>

#define B_  4
#define T_  2048
#define C_  1024
#define NH_ 16
#define D_  64
#define BT_ (B_ * T_)      // 8192
#define C3_ (3 * C_)       // 3072

// ---- persistent bf16 hi/lo operand storage (no allocation allowed) ----
__device__ __nv_bfloat16 g_xH[(size_t)BT_ * C_],  g_xL[(size_t)BT_ * C_];
__device__ __nv_bfloat16 g_WaH[(size_t)C_ * C3_], g_WaL[(size_t)C_ * C3_];
__device__ __nv_bfloat16 g_WpH[(size_t)C_ * C_],  g_WpL[(size_t)C_ * C_];
__device__ __nv_bfloat16 g_qkvH[(size_t)BT_ * C3_], g_qkvL[(size_t)BT_ * C3_];
__device__ __nv_bfloat16 g_yH[(size_t)BT_ * C_],  g_yL[(size_t)BT_ * C_];

// ---------------- bf16 helpers ----------------
__device__ __forceinline__ void split4bf(float4 v, uint2 &h, uint2 &l) {
    float e[4] = { v.x, v.y, v.z, v.w };
    unsigned hs[4], ls[4];
    #pragma unroll
    for (int i = 0; i < 4; i++) {
        __nv_bfloat16 bh = __float2bfloat16(e[i]);
        hs[i] = __bfloat16_as_ushort(bh);
        ls[i] = __bfloat16_as_ushort(__float2bfloat16(e[i] - __bfloat162float(bh)));
    }
    h.x = hs[0] | (hs[1] << 16);  h.y = hs[2] | (hs[3] << 16);
    l.x = ls[0] | (ls[1] << 16);  l.y = ls[2] | (ls[3] << 16);
}
__device__ __forceinline__ unsigned pk2bf(float a, float b) {
    return __bfloat16_as_ushort(__float2bfloat16(a)) |
           ((unsigned)__bfloat16_as_ushort(__float2bfloat16(b)) << 16);
}
__device__ __forceinline__ float bflo(float x) {
    return x - __bfloat162float(__float2bfloat16(x));
}
__device__ __forceinline__ void mmabf(float c[4], const unsigned a[4], const unsigned b[2]) {
    asm("mma.sync.aligned.m16n8k16.row.col.f32.bf16.bf16.f32 "
        "{%0,%1,%2,%3}, {%4,%5,%6,%7}, {%8,%9}, {%0,%1,%2,%3};"
        : "+f"(c[0]), "+f"(c[1]), "+f"(c[2]), "+f"(c[3])
        : "r"(a[0]), "r"(a[1]), "r"(a[2]), "r"(a[3]), "r"(b[0]), "r"(b[1]));
}
__device__ __forceinline__ void ldsm4(unsigned r[4], unsigned a) {
    asm volatile("ldmatrix.sync.aligned.m8n8.x4.shared.b16 {%0,%1,%2,%3}, [%4];"
        : "=r"(r[0]), "=r"(r[1]), "=r"(r[2]), "=r"(r[3]) : "r"(a));
}
__device__ __forceinline__ void ldsm4t(unsigned r[4], unsigned a) {
    asm volatile("ldmatrix.sync.aligned.m8n8.x4.trans.shared.b16 {%0,%1,%2,%3}, [%4];"
        : "=r"(r[0]), "=r"(r[1]), "=r"(r[2]), "=r"(r[3]) : "r"(a));
}
__device__ __forceinline__ unsigned sptr(const void* p) {
    return (unsigned)__cvta_generic_to_shared(p);
}
__device__ __forceinline__ void cp16(unsigned s, const void* g) {
    asm volatile("cp.async.ca.shared.global [%0], [%1], 16;" :: "r"(s), "l"(g));
}
__device__ __forceinline__ void cpcommit() { asm volatile("cp.async.commit_group;"); }
__device__ __forceinline__ void cpwait0()  { asm volatile("cp.async.wait_group 0;" ::: "memory"); }

// ---------------------------------------------------------------------------
// Prepass: split float -> bf16 hi/lo (n4 = n/4 float4 chunks)
// ---------------------------------------------------------------------------
__global__ void split_kernel(const float* __restrict__ src,
                             __nv_bfloat16* __restrict__ h,
                             __nv_bfloat16* __restrict__ l, int n4)
{
    int i = blockIdx.x * blockDim.x + threadIdx.x;
    if (i < n4) {
        float4 v = ((const float4*)src)[i];
        uint2 hh, ll; split4bf(v, hh, ll);
        ((uint2*)h)[i] = hh; ((uint2*)l)[i] = ll;
    }
}

// ---------------------------------------------------------------------------
// bf16x3 GEMM, pre-split operands, cp.async double buffer.
// BM=BN=128, BK=32, 8 warps (2x4), warp tile 64x32.
// smem (ushort units): AH st*5120 | AL 10240+st*5120 | BH 20480+st*4352 |
//                      BL 29184+st*4352.  Total 75776 B.
// MODE 0: qkv epilogue, writes bf16 hi/lo.  MODE 1: +b_proj, writes float.
// ---------------------------------------------------------------------------
template<int MODE>
__global__ __launch_bounds__(256) void gemm_bf16(
    const __nv_bfloat16* __restrict__ AHg, const __nv_bfloat16* __restrict__ ALg,
    const __nv_bfloat16* __restrict__ WHg, const __nv_bfloat16* __restrict__ WLg,
    const float* __restrict__ bias, const float* __restrict__ bQ,
    const float* __restrict__ bK, float* __restrict__ CoutF,
    __nv_bfloat16* __restrict__ CoutH, __nv_bfloat16* __restrict__ CoutL,
    int M, int N, int K)
{
    extern __shared__ __align__(16) unsigned short smg[];

    const int tid = threadIdx.x, lane = tid & 31, warp = tid >> 5;
    const int g = lane >> 2, c = lane & 3;
    const int wm = warp >> 2, wn = warp & 3;
    const int crow = blockIdx.y * 128, ccol = blockIdx.x * 128;

    float acc[4][4][4];
    #pragma unroll
    for (int i = 0; i < 4; i++)
        #pragma unroll
        for (int j = 0; j < 4; j++)
            #pragma unroll
            for (int f = 0; f < 4; f++) acc[i][j][f] = 0.f;

    // cp.async loader geometry: 2 chunks of 16B (8 bf16) per matrix per thread
    int ar[2], ac[2], br[2], bc[2];
    #pragma unroll
    for (int q = 0; q < 2; q++) {
        int cid = tid + 256 * q;
        ar[q] = cid >> 2;  ac[q] = (cid & 3) * 8;    // A: 128 rows x 32 (4 chunks/row)
        br[q] = cid >> 4;  bc[q] = (cid & 15) * 8;   // B: 32 rows x 128 (16 chunks/row)
    }
    const unsigned smbase = sptr(smg);

    // ldmatrix lane addresses (byte offsets, stage 0)
    const int rowA = wm * 64 + (lane & 7) + ((lane >> 3) & 1) * 8;
    const unsigned aAHb = smbase + (rowA * 40 + ((lane >> 4) & 1) * 8) * 2;
    const int rowB = (lane & 7) + ((lane >> 3) & 1) * 8;
    const int colB = wn * 32 + ((lane >> 4) & 1) * 8;
    const unsigned aBHb = smbase + (20480 + rowB * 136 + colB) * 2;

    const int nk = K >> 5;

    // tile loader
    auto load_tile = [&](int kt, int st) {
        #pragma unroll
        for (int q = 0; q < 2; q++) {
            unsigned sa = smbase + (st * 5120 + ar[q] * 40 + ac[q]) * 2;
            const __nv_bfloat16* ga = &AHg[(size_t)(crow + ar[q]) * K + kt * 32 + ac[q]];
            cp16(sa, ga);
            cp16(sa + 20480, &ALg[(size_t)(crow + ar[q]) * K + kt * 32 + ac[q]]);
            unsigned sb = smbase + (20480 + st * 4352 + br[q] * 136 + bc[q]) * 2;
            const __nv_bfloat16* gb = &WHg[(size_t)(kt * 32 + br[q]) * N + ccol + bc[q]];
            cp16(sb, gb);
            cp16(sb + 17408, &WLg[(size_t)(kt * 32 + br[q]) * N + ccol + bc[q]]);
        }
        cpcommit();
    };

    load_tile(0, 0);

    for (int kt = 0; kt < nk; kt++) {
        const int st = kt & 1;
        cpwait0();
        __syncthreads();
        if (kt + 1 < nk) load_tile(kt + 1, st ^ 1);

        const unsigned aA = aAHb + st * 10240;   // stage stride A = 5120 elem = 10240 B
        const unsigned aB = aBHb + st * 8704;    // stage stride B = 4352 elem = 8704 B
        #pragma unroll
        for (int ks = 0; ks < 2; ks++) {
            unsigned bh[4][2], bl[4][2];
            #pragma unroll
            for (int ntp = 0; ntp < 2; ntp++) {
                unsigned off = (ks * 16 * 136 + ntp * 16) * 2;
                unsigned t[4];
                ldsm4t(t, aB + off);
                bh[2 * ntp][0] = t[0]; bh[2 * ntp][1] = t[1];
                bh[2 * ntp + 1][0] = t[2]; bh[2 * ntp + 1][1] = t[3];
                ldsm4t(t, aB + 17408 + off);
                bl[2 * ntp][0] = t[0]; bl[2 * ntp][1] = t[1];
                bl[2 * ntp + 1][0] = t[2]; bl[2 * ntp + 1][1] = t[3];
            }
            #pragma unroll
            for (int mt = 0; mt < 4; mt++) {
                unsigned off = (mt * 16 * 40 + ks * 16) * 2;
                unsigned ah[4], al[4];
                ldsm4(ah, aA + off);
                ldsm4(al, aA + 20480 + off);
                #pragma unroll
                for (int nt = 0; nt < 4; nt++) {
                    mmabf(acc[mt][nt], ah, bh[nt]);
                    mmabf(acc[mt][nt], ah, bl[nt]);
                    mmabf(acc[mt][nt], al, bh[nt]);
                }
            }
        }
        __syncthreads();
    }

    // epilogue
    #pragma unroll
    for (int mt = 0; mt < 4; mt++)
    #pragma unroll
    for (int hh = 0; hh < 2; hh++) {
        int row = crow + wm * 64 + mt * 16 + g + 8 * hh;
        #pragma unroll
        for (int nt = 0; nt < 4; nt++) {
            int n0 = ccol + wn * 32 + nt * 8 + 2 * c;
            float v0 = acc[mt][nt][2 * hh]     + bias[n0];
            float v1 = acc[mt][nt][2 * hh + 1] + bias[n0 + 1];
            if (MODE == 0) {
                if (n0 < C_)          { v0 = (v0 + bQ[n0]) * 0.125f; v1 = (v1 + bQ[n0 + 1]) * 0.125f; }
                else if (n0 < 2 * C_) { v0 += bK[n0 - C_];           v1 += bK[n0 + 1 - C_]; }
                size_t o = (size_t)row * N + n0;
                *(unsigned*)&CoutH[o] = pk2bf(v0, v1);
                *(unsigned*)&CoutL[o] = pk2bf(bflo(v0), bflo(v1));
            } else {
                *(float2*)&CoutF[(size_t)row * N + n0] = make_float2(v0, v1);
            }
        }
    }
}

// ---------------------------------------------------------------------------
// Flash attention, bf16x3 mma + ldmatrix, pre-split q/k/v, P in registers.
// CTA = 128 q-rows x (h, b); 8 warps. Bk=64. smem 73728 B dynamic.
// ---------------------------------------------------------------------------
#define SQH 0
#define SQL (128 * 72)
#define SKH (2 * 128 * 72)
#define SKL (SKH + 64 * 72)
#define SVH (SKH + 2 * 64 * 72)
#define SVL (SVH + 64 * 72)
#define ASMEM_BYTES ((2 * 128 * 72 + 4 * 64 * 72) * 2)

__global__ __launch_bounds__(256) void attn_bf16()
{
    extern __shared__ __align__(16) unsigned short smn[];
    unsigned short *QH = smn + SQH, *QL = smn + SQL;
    unsigned short *KH = smn + SKH, *KL = smn + SKL;
    unsigned short *VH = smn + SVH, *VL = smn + SVL;

    const int tid = threadIdx.x, lane = tid & 31, w = tid >> 5;
    const int g = lane >> 2, c = lane & 3;
    const int qt = blockIdx.x, h = blockIdx.y, b = blockIdx.z;
    const int q0 = qt * 128;
    const size_t rb = (size_t)b * T_ * C3_ + (size_t)h * D_;

    // Q fill (already hi/lo in gmem)
    #pragma unroll
    for (int r = 0; r < 8; r++) {
        int idx = tid + 256 * r;
        int qq = idx >> 4, d0 = (idx & 15) * 4;
        size_t gi = rb + (size_t)(q0 + qq) * C3_ + d0;
        *(uint2*)&QH[qq * 72 + d0] = *(const uint2*)&g_qkvH[gi];
        *(uint2*)&QL[qq * 72 + d0] = *(const uint2*)&g_qkvL[gi];
    }

    const int rQ = w * 16 + (lane & 7) + ((lane >> 3) & 1) * 8;
    const unsigned qOff = (rQ * 72 + ((lane >> 4) & 1) * 8) * 2;
    const int rK = (lane & 7) + ((lane >> 4) & 1) * 8;
    const unsigned kOff = (rK * 72 + ((lane >> 3) & 1) * 8) * 2;
    const int rV = (lane & 7) + ((lane >> 3) & 1) * 8;
    const unsigned vOff = (rV * 72 + ((lane >> 4) & 1) * 8) * 2;
    const unsigned aQH = sptr(QH) + qOff, aQL = sptr(QL) + qOff;
    const unsigned aKH = sptr(KH) + kOff, aKL = sptr(KL) + kOff;
    const unsigned aVH = sptr(VH) + vOff, aVL = sptr(VL) + vOff;

    float m0 = -1e30f, m1 = -1e30f, l0 = 0.f, l1 = 0.f;
    float o[8][4];
    #pragma unroll
    for (int nt = 0; nt < 8; nt++)
        #pragma unroll
        for (int f = 0; f < 4; f++) o[nt][f] = 0.f;

    const int row0 = q0 + w * 16 + g, row1 = row0 + 8;
    const int nkt = 2 * qt + 2;

    for (int kt = 0; kt < nkt; kt++) {
        __syncthreads();
        #pragma unroll
        for (int r = 0; r < 4; r++) {
            int idx = tid + 256 * r;
            int kc = idx >> 4, d0 = (idx & 15) * 4;
            size_t go = rb + (size_t)(kt * 64 + kc) * C3_;
            *(uint2*)&KH[kc * 72 + d0] = *(const uint2*)&g_qkvH[go + C_ + d0];
            *(uint2*)&KL[kc * 72 + d0] = *(const uint2*)&g_qkvL[go + C_ + d0];
            *(uint2*)&VH[kc * 72 + d0] = *(const uint2*)&g_qkvH[go + 2 * C_ + d0];
            *(uint2*)&VL[kc * 72 + d0] = *(const uint2*)&g_qkvL[go + 2 * C_ + d0];
        }
        __syncthreads();

        // ---- S = Q K^T (3-term) ----
        float s[8][4];
        #pragma unroll
        for (int nt = 0; nt < 8; nt++)
            #pragma unroll
            for (int f = 0; f < 4; f++) s[nt][f] = 0.f;

        #pragma unroll
        for (int ks = 0; ks < 4; ks++) {
            unsigned qh[4], ql[4];
            ldsm4(qh, aQH + ks * 32);
            ldsm4(ql, aQL + ks * 32);
            unsigned bh[8][2], bl[8][2];
            #pragma unroll
            for (int ntp = 0; ntp < 4; ntp++) {
                unsigned off = (ntp * 16 * 72 + ks * 16) * 2;
                unsigned t[4];
                ldsm4(t, aKH + off);
                bh[2 * ntp][0] = t[0]; bh[2 * ntp][1] = t[1];
                bh[2 * ntp + 1][0] = t[2]; bh[2 * ntp + 1][1] = t[3];
                ldsm4(t, aKL + off);
                bl[2 * ntp][0] = t[0]; bl[2 * ntp][1] = t[1];
                bl[2 * ntp + 1][0] = t[2]; bl[2 * ntp + 1][1] = t[3];
            }
            #pragma unroll
            for (int nt = 0; nt < 8; nt++) {
                mmabf(s[nt], qh, bh[nt]);
                mmabf(s[nt], qh, bl[nt]);
                mmabf(s[nt], ql, bh[nt]);
            }
        }

        if (kt >= 2 * qt) {
            #pragma unroll
            for (int nt = 0; nt < 8; nt++) {
                int col = kt * 64 + nt * 8 + 2 * c;
                if (col     > row0) s[nt][0] = -1e30f;
                if (col + 1 > row0) s[nt][1] = -1e30f;
                if (col     > row1) s[nt][2] = -1e30f;
                if (col + 1 > row1) s[nt][3] = -1e30f;
            }
        }

        // ---- online softmax ----
        float mx0 = -1e30f, mx1 = -1e30f;
        #pragma unroll
        for (int nt = 0; nt < 8; nt++) {
            mx0 = fmaxf(mx0, fmaxf(s[nt][0], s[nt][1]));
            mx1 = fmaxf(mx1, fmaxf(s[nt][2], s[nt][3]));
        }
        mx0 = fmaxf(mx0, __shfl_xor_sync(0xffffffffu, mx0, 1));
        mx0 = fmaxf(mx0, __shfl_xor_sync(0xffffffffu, mx0, 2));
        mx1 = fmaxf(mx1, __shfl_xor_sync(0xffffffffu, mx1, 1));
        mx1 = fmaxf(mx1, __shfl_xor_sync(0xffffffffu, mx1, 2));
        float mn0 = fmaxf(m0, mx0), mn1 = fmaxf(m1, mx1);
        float a0 = __expf(m0 - mn0), a1 = __expf(m1 - mn1);
        float sum0 = 0.f, sum1 = 0.f;
        #pragma unroll
        for (int nt = 0; nt < 8; nt++) {
            s[nt][0] = __expf(s[nt][0] - mn0);
            s[nt][1] = __expf(s[nt][1] - mn0);
            s[nt][2] = __expf(s[nt][2] - mn1);
            s[nt][3] = __expf(s[nt][3] - mn1);
            sum0 += s[nt][0] + s[nt][1];
            sum1 += s[nt][2] + s[nt][3];
        }
        sum0 += __shfl_xor_sync(0xffffffffu, sum0, 1);
        sum0 += __shfl_xor_sync(0xffffffffu, sum0, 2);
        sum1 += __shfl_xor_sync(0xffffffffu, sum1, 1);
        sum1 += __shfl_xor_sync(0xffffffffu, sum1, 2);
        l0 = l0 * a0 + sum0;  m0 = mn0;
        l1 = l1 * a1 + sum1;  m1 = mn1;
        #pragma unroll
        for (int nt = 0; nt < 8; nt++) {
            o[nt][0] *= a0; o[nt][1] *= a0;
            o[nt][2] *= a1; o[nt][3] *= a1;
        }

        // ---- P in registers (hi + lo) ----
        unsigned ph[8][2], pl[8][2];
        #pragma unroll
        for (int nt = 0; nt < 8; nt++) {
            ph[nt][0] = pk2bf(s[nt][0], s[nt][1]);
            ph[nt][1] = pk2bf(s[nt][2], s[nt][3]);
            pl[nt][0] = pk2bf(bflo(s[nt][0]), bflo(s[nt][1]));
            pl[nt][1] = pk2bf(bflo(s[nt][2]), bflo(s[nt][3]));
        }

        // ---- O += P V (3-term) ----
        #pragma unroll
        for (int ks = 0; ks < 4; ks++) {
            unsigned pah[4] = { ph[2 * ks][0], ph[2 * ks][1], ph[2 * ks + 1][0], ph[2 * ks + 1][1] };
            unsigned pal[4] = { pl[2 * ks][0], pl[2 * ks][1], pl[2 * ks + 1][0], pl[2 * ks + 1][1] };
            unsigned bh[8][2], bl[8][2];
            #pragma unroll
            for (int ntp = 0; ntp < 4; ntp++) {
                unsigned off = (ks * 16 * 72 + ntp * 16) * 2;
                unsigned t[4];
                ldsm4t(t, aVH + off);
                bh[2 * ntp][0] = t[0]; bh[2 * ntp][1] = t[1];
                bh[2 * ntp + 1][0] = t[2]; bh[2 * ntp + 1][1] = t[3];
                ldsm4t(t, aVL + off);
                bl[2 * ntp][0] = t[0]; bl[2 * ntp][1] = t[1];
                bl[2 * ntp + 1][0] = t[2]; bl[2 * ntp + 1][1] = t[3];
            }
            #pragma unroll
            for (int nt = 0; nt < 8; nt++) {
                mmabf(o[nt], pah, bh[nt]);
                mmabf(o[nt], pah, bl[nt]);
                mmabf(o[nt], pal, bh[nt]);
            }
        }
    }

    // normalize + write yH/yL (bf16 hi/lo) in [b*T+row][h*64 + d]
    float i0 = 1.f / l0, i1 = 1.f / l1;
    #pragma unroll
    for (int nt = 0; nt < 8; nt++) {
        int col = h * D_ + nt * 8 + 2 * c;
        float y00 = o[nt][0] * i0, y01 = o[nt][1] * i0;
        float y10 = o[nt][2] * i1, y11 = o[nt][3] * i1;
        size_t o0 = (size_t)(b * T_ + row0) * C_ + col;
        size_t o1 = (size_t)(b * T_ + row1) * C_ + col;
        *(unsigned*)&g_yH[o0] = pk2bf(y00, y01);
        *(unsigned*)&g_yL[o0] = pk2bf(bflo(y00), bflo(y01));
        *(unsigned*)&g_yH[o1] = pk2bf(y10, y11);
        *(unsigned*)&g_yL[o1] = pk2bf(bflo(y10), bflo(y11));
    }
}

// ---------------------------------------------------------------------------
#define GSMEM_BYTES 75776

extern "C" void kernel_launch(void* const* d_in, const int* in_sizes, int n_in,
                              void* d_out, int out_size)
{
    const float* x      = (const float*)d_in[0];
    const float* W_attn = (const float*)d_in[1];
    const float* b_attn = (const float*)d_in[2];
    const float* bQ     = (const float*)d_in[3];
    const float* bK     = (const float*)d_in[4];
    const float* W_proj = (const float*)d_in[5];
    const float* b_proj = (const float*)d_in[6];
    float* out = (float*)d_out;

    __nv_bfloat16 *xH, *xL, *WaH, *WaL, *WpH, *WpL, *qkvH, *qkvL, *yH, *yL;
    cudaGetSymbolAddress((void**)&xH, g_xH);     cudaGetSymbolAddress((void**)&xL, g_xL);
    cudaGetSymbolAddress((void**)&WaH, g_WaH);   cudaGetSymbolAddress((void**)&WaL, g_WaL);
    cudaGetSymbolAddress((void**)&WpH, g_WpH);   cudaGetSymbolAddress((void**)&WpL, g_WpL);
    cudaGetSymbolAddress((void**)&qkvH, g_qkvH); cudaGetSymbolAddress((void**)&qkvL, g_qkvL);
    cudaGetSymbolAddress((void**)&yH, g_yH);     cudaGetSymbolAddress((void**)&yL, g_yL);

    cudaFuncSetAttribute(gemm_bf16<0>, cudaFuncAttributeMaxDynamicSharedMemorySize, GSMEM_BYTES);
    cudaFuncSetAttribute(gemm_bf16<1>, cudaFuncAttributeMaxDynamicSharedMemorySize, GSMEM_BYTES);
    cudaFuncSetAttribute(attn_bf16, cudaFuncAttributeMaxDynamicSharedMemorySize, ASMEM_BYTES);

    // prepass: split operands once
    {
        int n4x = BT_ * C_ / 4, n4a = C_ * C3_ / 4, n4p = C_ * C_ / 4;
        split_kernel<<<(n4x + 255) / 256, 256>>>(x, xH, xL, n4x);
        split_kernel<<<(n4a + 255) / 256, 256>>>(W_attn, WaH, WaL, n4a);
        split_kernel<<<(n4p + 255) / 256, 256>>>(W_proj, WpH, WpL, n4p);
    }

    // 1) qkv (bf16 hi/lo out)
    gemm_bf16<0><<<dim3(C3_ / 128, BT_ / 128), 256, GSMEM_BYTES>>>(
        xH, xL, WaH, WaL, b_attn, bQ, bK, nullptr, qkvH, qkvL, BT_, C3_, C_);

    // 2) flash attention (bf16 hi/lo out)
    attn_bf16<<<dim3(T_ / 128, NH_, B_), 256, ASMEM_BYTES>>>();

    // 3) proj (float out)
    gemm_bf16<1><<<dim3(C_ / 128, BT_ / 128), 256, GSMEM_BYTES>>>(
        yH, yL, WpH, WpL, b_proj, nullptr, nullptr, out, nullptr, nullptr, BT_, C_, C_);
}

// round 9
// speedup vs baseline: 2.8143x; 1.0815x over previous
#include <cuda_runtime.h>
#include <cuda_bf16.h>

#define B_  4
#define T_  2048
#define C_  1024
#define NH_ 16
#define D_  64
#define BT_ (B_ * T_)      // 8192
#define C3_ (3 * C_)       // 3072

// ---- persistent bf16 hi/lo operand storage (no allocation allowed) ----
__device__ __nv_bfloat16 g_xH[(size_t)BT_ * C_],  g_xL[(size_t)BT_ * C_];
__device__ __nv_bfloat16 g_WaH[(size_t)C_ * C3_], g_WaL[(size_t)C_ * C3_];
__device__ __nv_bfloat16 g_WpH[(size_t)C_ * C_],  g_WpL[(size_t)C_ * C_];
__device__ __nv_bfloat16 g_qkvH[(size_t)BT_ * C3_], g_qkvL[(size_t)BT_ * C3_];
__device__ __nv_bfloat16 g_yH[(size_t)BT_ * C_],  g_yL[(size_t)BT_ * C_];

// ---------------- bf16 helpers ----------------
__device__ __forceinline__ void split4bf(float4 v, uint2 &h, uint2 &l) {
    float e[4] = { v.x, v.y, v.z, v.w };
    unsigned hs[4], ls[4];
    #pragma unroll
    for (int i = 0; i < 4; i++) {
        __nv_bfloat16 bh = __float2bfloat16(e[i]);
        hs[i] = __bfloat16_as_ushort(bh);
        ls[i] = __bfloat16_as_ushort(__float2bfloat16(e[i] - __bfloat162float(bh)));
    }
    h.x = hs[0] | (hs[1] << 16);  h.y = hs[2] | (hs[3] << 16);
    l.x = ls[0] | (ls[1] << 16);  l.y = ls[2] | (ls[3] << 16);
}
__device__ __forceinline__ unsigned pk2bf(float a, float b) {
    return __bfloat16_as_ushort(__float2bfloat16(a)) |
           ((unsigned)__bfloat16_as_ushort(__float2bfloat16(b)) << 16);
}
__device__ __forceinline__ float bflo(float x) {
    return x - __bfloat162float(__float2bfloat16(x));
}
__device__ __forceinline__ void mmabf(float c[4], const unsigned a[4], const unsigned b[2]) {
    asm("mma.sync.aligned.m16n8k16.row.col.f32.bf16.bf16.f32 "
        "{%0,%1,%2,%3}, {%4,%5,%6,%7}, {%8,%9}, {%0,%1,%2,%3};"
        : "+f"(c[0]), "+f"(c[1]), "+f"(c[2]), "+f"(c[3])
        : "r"(a[0]), "r"(a[1]), "r"(a[2]), "r"(a[3]), "r"(b[0]), "r"(b[1]));
}
__device__ __forceinline__ void ldsm4(unsigned r[4], unsigned a) {
    asm volatile("ldmatrix.sync.aligned.m8n8.x4.shared.b16 {%0,%1,%2,%3}, [%4];"
        : "=r"(r[0]), "=r"(r[1]), "=r"(r[2]), "=r"(r[3]) : "r"(a));
}
__device__ __forceinline__ void ldsm4t(unsigned r[4], unsigned a) {
    asm volatile("ldmatrix.sync.aligned.m8n8.x4.trans.shared.b16 {%0,%1,%2,%3}, [%4];"
        : "=r"(r[0]), "=r"(r[1]), "=r"(r[2]), "=r"(r[3]) : "r"(a));
}
__device__ __forceinline__ unsigned sptr(const void* p) {
    return (unsigned)__cvta_generic_to_shared(p);
}
__device__ __forceinline__ void cp16(unsigned s, const void* g) {
    asm volatile("cp.async.ca.shared.global [%0], [%1], 16;" :: "r"(s), "l"(g));
}
__device__ __forceinline__ void cpcommit() { asm volatile("cp.async.commit_group;"); }
__device__ __forceinline__ void cpwait0()  { asm volatile("cp.async.wait_group 0;" ::: "memory"); }
__device__ __forceinline__ void cpwait1()  { asm volatile("cp.async.wait_group 1;" ::: "memory"); }

// ---------------------------------------------------------------------------
// Prepass: split float -> bf16 hi/lo
// ---------------------------------------------------------------------------
__global__ void split_kernel(const float* __restrict__ src,
                             __nv_bfloat16* __restrict__ h,
                             __nv_bfloat16* __restrict__ l, int n4)
{
    int i = blockIdx.x * blockDim.x + threadIdx.x;
    if (i < n4) {
        float4 v = ((const float4*)src)[i];
        uint2 hh, ll; split4bf(v, hh, ll);
        ((uint2*)h)[i] = hh; ((uint2*)l)[i] = ll;
    }
}

// ---------------------------------------------------------------------------
// bf16x3 GEMM (unchanged from R7): pre-split operands, cp.async double buffer.
// ---------------------------------------------------------------------------
template<int MODE>
__global__ __launch_bounds__(256) void gemm_bf16(
    const __nv_bfloat16* __restrict__ AHg, const __nv_bfloat16* __restrict__ ALg,
    const __nv_bfloat16* __restrict__ WHg, const __nv_bfloat16* __restrict__ WLg,
    const float* __restrict__ bias, const float* __restrict__ bQ,
    const float* __restrict__ bK, float* __restrict__ CoutF,
    __nv_bfloat16* __restrict__ CoutH, __nv_bfloat16* __restrict__ CoutL,
    int M, int N, int K)
{
    extern __shared__ __align__(16) unsigned short smg[];

    const int tid = threadIdx.x, lane = tid & 31, warp = tid >> 5;
    const int g = lane >> 2, c = lane & 3;
    const int wm = warp >> 2, wn = warp & 3;
    const int crow = blockIdx.y * 128, ccol = blockIdx.x * 128;

    float acc[4][4][4];
    #pragma unroll
    for (int i = 0; i < 4; i++)
        #pragma unroll
        for (int j = 0; j < 4; j++)
            #pragma unroll
            for (int f = 0; f < 4; f++) acc[i][j][f] = 0.f;

    int ar[2], ac[2], br[2], bc[2];
    #pragma unroll
    for (int q = 0; q < 2; q++) {
        int cid = tid + 256 * q;
        ar[q] = cid >> 2;  ac[q] = (cid & 3) * 8;
        br[q] = cid >> 4;  bc[q] = (cid & 15) * 8;
    }
    const unsigned smbase = sptr(smg);

    const int rowA = wm * 64 + (lane & 7) + ((lane >> 3) & 1) * 8;
    const unsigned aAHb = smbase + (rowA * 40 + ((lane >> 4) & 1) * 8) * 2;
    const int rowB = (lane & 7) + ((lane >> 3) & 1) * 8;
    const int colB = wn * 32 + ((lane >> 4) & 1) * 8;
    const unsigned aBHb = smbase + (20480 + rowB * 136 + colB) * 2;

    const int nk = K >> 5;

    auto load_tile = [&](int kt, int st) {
        #pragma unroll
        for (int q = 0; q < 2; q++) {
            unsigned sa = smbase + (st * 5120 + ar[q] * 40 + ac[q]) * 2;
            cp16(sa, &AHg[(size_t)(crow + ar[q]) * K + kt * 32 + ac[q]]);
            cp16(sa + 20480, &ALg[(size_t)(crow + ar[q]) * K + kt * 32 + ac[q]]);
            unsigned sb = smbase + (20480 + st * 4352 + br[q] * 136 + bc[q]) * 2;
            cp16(sb, &WHg[(size_t)(kt * 32 + br[q]) * N + ccol + bc[q]]);
            cp16(sb + 17408, &WLg[(size_t)(kt * 32 + br[q]) * N + ccol + bc[q]]);
        }
        cpcommit();
    };

    load_tile(0, 0);

    for (int kt = 0; kt < nk; kt++) {
        const int st = kt & 1;
        cpwait0();
        __syncthreads();
        if (kt + 1 < nk) load_tile(kt + 1, st ^ 1);

        const unsigned aA = aAHb + st * 10240;
        const unsigned aB = aBHb + st * 8704;
        #pragma unroll
        for (int ks = 0; ks < 2; ks++) {
            unsigned bh[4][2], bl[4][2];
            #pragma unroll
            for (int ntp = 0; ntp < 2; ntp++) {
                unsigned off = (ks * 16 * 136 + ntp * 16) * 2;
                unsigned t[4];
                ldsm4t(t, aB + off);
                bh[2 * ntp][0] = t[0]; bh[2 * ntp][1] = t[1];
                bh[2 * ntp + 1][0] = t[2]; bh[2 * ntp + 1][1] = t[3];
                ldsm4t(t, aB + 17408 + off);
                bl[2 * ntp][0] = t[0]; bl[2 * ntp][1] = t[1];
                bl[2 * ntp + 1][0] = t[2]; bl[2 * ntp + 1][1] = t[3];
            }
            #pragma unroll
            for (int mt = 0; mt < 4; mt++) {
                unsigned off = (mt * 16 * 40 + ks * 16) * 2;
                unsigned ah[4], al[4];
                ldsm4(ah, aA + off);
                ldsm4(al, aA + 20480 + off);
                #pragma unroll
                for (int nt = 0; nt < 4; nt++) {
                    mmabf(acc[mt][nt], ah, bh[nt]);
                    mmabf(acc[mt][nt], ah, bl[nt]);
                    mmabf(acc[mt][nt], al, bh[nt]);
                }
            }
        }
        __syncthreads();
    }

    #pragma unroll
    for (int mt = 0; mt < 4; mt++)
    #pragma unroll
    for (int hh = 0; hh < 2; hh++) {
        int row = crow + wm * 64 + mt * 16 + g + 8 * hh;
        #pragma unroll
        for (int nt = 0; nt < 4; nt++) {
            int n0 = ccol + wn * 32 + nt * 8 + 2 * c;
            float v0 = acc[mt][nt][2 * hh]     + bias[n0];
            float v1 = acc[mt][nt][2 * hh + 1] + bias[n0 + 1];
            if (MODE == 0) {
                if (n0 < C_)          { v0 = (v0 + bQ[n0]) * 0.125f; v1 = (v1 + bQ[n0 + 1]) * 0.125f; }
                else if (n0 < 2 * C_) { v0 += bK[n0 - C_];           v1 += bK[n0 + 1 - C_]; }
                size_t o = (size_t)row * N + n0;
                *(unsigned*)&CoutH[o] = pk2bf(v0, v1);
                *(unsigned*)&CoutL[o] = pk2bf(bflo(v0), bflo(v1));
            } else {
                *(float2*)&CoutF[(size_t)row * N + n0] = make_float2(v0, v1);
            }
        }
    }
}

// ---------------------------------------------------------------------------
// Flash attention, bf16x3 + ldmatrix, cp.async 3-stage K/V ring.
// CTA = 128 q-rows x (h, b); 8 warps. Bk=64.
// smem (ush): QH 0 | QL 9216 | KV stage s at 18432 + s*18432,
//   within stage: KH 0 | KL 4608 | VH 9216 | VL 13824.   Total 147456 B.
// ---------------------------------------------------------------------------
#define ASMEM_BYTES 147456

__global__ __launch_bounds__(256) void attn_bf16()
{
    extern __shared__ __align__(16) unsigned short smn[];
    const unsigned smbase = sptr(smn);

    const int tid = threadIdx.x, lane = tid & 31, w = tid >> 5;
    const int g = lane >> 2, c = lane & 3;
    const int qt = blockIdx.x, h = blockIdx.y, b = blockIdx.z;
    const int q0 = qt * 128;
    const size_t rb = (size_t)b * T_ * C3_ + (size_t)h * D_;

    const int nkt = 2 * qt + 2;

    // K/V tile loader: 2 chunks x 4 matrices per thread, one commit group
    auto load_kv = [&](int kt, int st) {
        #pragma unroll
        for (int q = 0; q < 2; q++) {
            int idx = tid + 256 * q;
            int kc = idx >> 3, d0 = (idx & 7) * 8;
            size_t go = rb + (size_t)(kt * 64 + kc) * C3_ + d0;
            unsigned sb = smbase + (18432 + kc * 72 + d0) * 2 + st * 36864;
            cp16(sb,          &g_qkvH[go + C_]);
            cp16(sb + 9216,   &g_qkvL[go + C_]);
            cp16(sb + 18432,  &g_qkvH[go + 2 * C_]);
            cp16(sb + 27648,  &g_qkvL[go + 2 * C_]);
        }
        cpcommit();
    };

    // Prologue: Q (cp.async) + KV tile 0 as group 0; KV tile 1 as group 1
    #pragma unroll
    for (int r = 0; r < 4; r++) {
        int idx = tid + 256 * r;
        int qq = idx >> 3, d0 = (idx & 7) * 8;
        size_t gi = rb + (size_t)(q0 + qq) * C3_ + d0;
        unsigned sb = smbase + (qq * 72 + d0) * 2;
        cp16(sb, &g_qkvH[gi]);
        cp16(sb + 18432, &g_qkvL[gi]);
    }
    load_kv(0, 0);      // commits group 0 (Q + KV0)
    load_kv(1, 1);      // group 1

    // ldmatrix lane addresses
    const int rQ = w * 16 + (lane & 7) + ((lane >> 3) & 1) * 8;
    const unsigned aQH = smbase + (rQ * 72 + ((lane >> 4) & 1) * 8) * 2;
    const unsigned aQL = aQH + 18432;
    const int rK = (lane & 7) + ((lane >> 4) & 1) * 8;
    const unsigned kOff = (18432 + rK * 72 + ((lane >> 3) & 1) * 8) * 2;
    const int rV = (lane & 7) + ((lane >> 3) & 1) * 8;
    const unsigned vOff = (18432 + 9216 + rV * 72 + ((lane >> 4) & 1) * 8) * 2;

    float m0 = -1e30f, m1 = -1e30f, l0 = 0.f, l1 = 0.f;
    float o[8][4];
    #pragma unroll
    for (int nt = 0; nt < 8; nt++)
        #pragma unroll
        for (int f = 0; f < 4; f++) o[nt][f] = 0.f;

    const int row0 = q0 + w * 16 + g, row1 = row0 + 8;

    for (int kt = 0; kt < nkt; kt++) {
        const int st = kt % 3;
        cpwait1();            // stage kt resident (<=1 younger group pending)
        __syncthreads();
        if (kt + 2 < nkt) load_kv(kt + 2, (kt + 2) % 3);

        const unsigned aKH = smbase + kOff + st * 36864;
        const unsigned aKL = aKH + 9216;
        const unsigned aVH = smbase + vOff + st * 36864;
        const unsigned aVL = aVH + 9216;

        // ---- S = Q K^T (3-term) ----
        float s[8][4];
        #pragma unroll
        for (int nt = 0; nt < 8; nt++)
            #pragma unroll
            for (int f = 0; f < 4; f++) s[nt][f] = 0.f;

        #pragma unroll
        for (int ks = 0; ks < 4; ks++) {
            unsigned qh[4], ql[4];
            ldsm4(qh, aQH + ks * 32);
            ldsm4(ql, aQL + ks * 32);
            unsigned bh[8][2], bl[8][2];
            #pragma unroll
            for (int ntp = 0; ntp < 4; ntp++) {
                unsigned off = (ntp * 16 * 72 + ks * 16) * 2;
                unsigned t[4];
                ldsm4(t, aKH + off);
                bh[2 * ntp][0] = t[0]; bh[2 * ntp][1] = t[1];
                bh[2 * ntp + 1][0] = t[2]; bh[2 * ntp + 1][1] = t[3];
                ldsm4(t, aKL + off);
                bl[2 * ntp][0] = t[0]; bl[2 * ntp][1] = t[1];
                bl[2 * ntp + 1][0] = t[2]; bl[2 * ntp + 1][1] = t[3];
            }
            #pragma unroll
            for (int nt = 0; nt < 8; nt++) {
                mmabf(s[nt], qh, bh[nt]);
                mmabf(s[nt], qh, bl[nt]);
                mmabf(s[nt], ql, bh[nt]);
            }
        }

        if (kt >= 2 * qt) {
            #pragma unroll
            for (int nt = 0; nt < 8; nt++) {
                int col = kt * 64 + nt * 8 + 2 * c;
                if (col     > row0) s[nt][0] = -1e30f;
                if (col + 1 > row0) s[nt][1] = -1e30f;
                if (col     > row1) s[nt][2] = -1e30f;
                if (col + 1 > row1) s[nt][3] = -1e30f;
            }
        }

        // ---- online softmax ----
        float mx0 = -1e30f, mx1 = -1e30f;
        #pragma unroll
        for (int nt = 0; nt < 8; nt++) {
            mx0 = fmaxf(mx0, fmaxf(s[nt][0], s[nt][1]));
            mx1 = fmaxf(mx1, fmaxf(s[nt][2], s[nt][3]));
        }
        mx0 = fmaxf(mx0, __shfl_xor_sync(0xffffffffu, mx0, 1));
        mx0 = fmaxf(mx0, __shfl_xor_sync(0xffffffffu, mx0, 2));
        mx1 = fmaxf(mx1, __shfl_xor_sync(0xffffffffu, mx1, 1));
        mx1 = fmaxf(mx1, __shfl_xor_sync(0xffffffffu, mx1, 2));
        float mn0 = fmaxf(m0, mx0), mn1 = fmaxf(m1, mx1);
        float a0 = __expf(m0 - mn0), a1 = __expf(m1 - mn1);
        float sum0 = 0.f, sum1 = 0.f;
        #pragma unroll
        for (int nt = 0; nt < 8; nt++) {
            s[nt][0] = __expf(s[nt][0] - mn0);
            s[nt][1] = __expf(s[nt][1] - mn0);
            s[nt][2] = __expf(s[nt][2] - mn1);
            s[nt][3] = __expf(s[nt][3] - mn1);
            sum0 += s[nt][0] + s[nt][1];
            sum1 += s[nt][2] + s[nt][3];
        }
        sum0 += __shfl_xor_sync(0xffffffffu, sum0, 1);
        sum0 += __shfl_xor_sync(0xffffffffu, sum0, 2);
        sum1 += __shfl_xor_sync(0xffffffffu, sum1, 1);
        sum1 += __shfl_xor_sync(0xffffffffu, sum1, 2);
        l0 = l0 * a0 + sum0;  m0 = mn0;
        l1 = l1 * a1 + sum1;  m1 = mn1;
        #pragma unroll
        for (int nt = 0; nt < 8; nt++) {
            o[nt][0] *= a0; o[nt][1] *= a0;
            o[nt][2] *= a1; o[nt][3] *= a1;
        }

        // ---- P in registers (hi + lo) ----
        unsigned ph[8][2], pl[8][2];
        #pragma unroll
        for (int nt = 0; nt < 8; nt++) {
            ph[nt][0] = pk2bf(s[nt][0], s[nt][1]);
            ph[nt][1] = pk2bf(s[nt][2], s[nt][3]);
            pl[nt][0] = pk2bf(bflo(s[nt][0]), bflo(s[nt][1]));
            pl[nt][1] = pk2bf(bflo(s[nt][2]), bflo(s[nt][3]));
        }

        // ---- O += P V (3-term) ----
        #pragma unroll
        for (int ks = 0; ks < 4; ks++) {
            unsigned pah[4] = { ph[2 * ks][0], ph[2 * ks][1], ph[2 * ks + 1][0], ph[2 * ks + 1][1] };
            unsigned pal[4] = { pl[2 * ks][0], pl[2 * ks][1], pl[2 * ks + 1][0], pl[2 * ks + 1][1] };
            unsigned bh[8][2], bl[8][2];
            #pragma unroll
            for (int ntp = 0; ntp < 4; ntp++) {
                unsigned off = (ks * 16 * 72 + ntp * 16) * 2;
                unsigned t[4];
                ldsm4t(t, aVH + off);
                bh[2 * ntp][0] = t[0]; bh[2 * ntp][1] = t[1];
                bh[2 * ntp + 1][0] = t[2]; bh[2 * ntp + 1][1] = t[3];
                ldsm4t(t, aVL + off);
                bl[2 * ntp][0] = t[0]; bl[2 * ntp][1] = t[1];
                bl[2 * ntp + 1][0] = t[2]; bl[2 * ntp + 1][1] = t[3];
            }
            #pragma unroll
            for (int nt = 0; nt < 8; nt++) {
                mmabf(o[nt], pah, bh[nt]);
                mmabf(o[nt], pah, bl[nt]);
                mmabf(o[nt], pal, bh[nt]);
            }
        }
    }

    // normalize + write yH/yL
    float i0 = 1.f / l0, i1 = 1.f / l1;
    #pragma unroll
    for (int nt = 0; nt < 8; nt++) {
        int col = h * D_ + nt * 8 + 2 * c;
        float y00 = o[nt][0] * i0, y01 = o[nt][1] * i0;
        float y10 = o[nt][2] * i1, y11 = o[nt][3] * i1;
        size_t o0 = (size_t)(b * T_ + row0) * C_ + col;
        size_t o1 = (size_t)(b * T_ + row1) * C_ + col;
        *(unsigned*)&g_yH[o0] = pk2bf(y00, y01);
        *(unsigned*)&g_yL[o0] = pk2bf(bflo(y00), bflo(y01));
        *(unsigned*)&g_yH[o1] = pk2bf(y10, y11);
        *(unsigned*)&g_yL[o1] = pk2bf(bflo(y10), bflo(y11));
    }
}

// ---------------------------------------------------------------------------
#define GSMEM_BYTES 75776

extern "C" void kernel_launch(void* const* d_in, const int* in_sizes, int n_in,
                              void* d_out, int out_size)
{
    const float* x      = (const float*)d_in[0];
    const float* W_attn = (const float*)d_in[1];
    const float* b_attn = (const float*)d_in[2];
    const float* bQ     = (const float*)d_in[3];
    const float* bK     = (const float*)d_in[4];
    const float* W_proj = (const float*)d_in[5];
    const float* b_proj = (const float*)d_in[6];
    float* out = (float*)d_out;

    __nv_bfloat16 *xH, *xL, *WaH, *WaL, *WpH, *WpL, *qkvH, *qkvL, *yH, *yL;
    cudaGetSymbolAddress((void**)&xH, g_xH);     cudaGetSymbolAddress((void**)&xL, g_xL);
    cudaGetSymbolAddress((void**)&WaH, g_WaH);   cudaGetSymbolAddress((void**)&WaL, g_WaL);
    cudaGetSymbolAddress((void**)&WpH, g_WpH);   cudaGetSymbolAddress((void**)&WpL, g_WpL);
    cudaGetSymbolAddress((void**)&qkvH, g_qkvH); cudaGetSymbolAddress((void**)&qkvL, g_qkvL);
    cudaGetSymbolAddress((void**)&yH, g_yH);     cudaGetSymbolAddress((void**)&yL, g_yL);

    cudaFuncSetAttribute(gemm_bf16<0>, cudaFuncAttributeMaxDynamicSharedMemorySize, GSMEM_BYTES);
    cudaFuncSetAttribute(gemm_bf16<1>, cudaFuncAttributeMaxDynamicSharedMemorySize, GSMEM_BYTES);
    cudaFuncSetAttribute(attn_bf16, cudaFuncAttributeMaxDynamicSharedMemorySize, ASMEM_BYTES);

    // prepass: split operands once
    {
        int n4x = BT_ * C_ / 4, n4a = C_ * C3_ / 4, n4p = C_ * C_ / 4;
        split_kernel<<<(n4x + 255) / 256, 256>>>(x, xH, xL, n4x);
        split_kernel<<<(n4a + 255) / 256, 256>>>(W_attn, WaH, WaL, n4a);
        split_kernel<<<(n4p + 255) / 256, 256>>>(W_proj, WpH, WpL, n4p);
    }

    // 1) qkv (bf16 hi/lo out)
    gemm_bf16<0><<<dim3(C3_ / 128, BT_ / 128), 256, GSMEM_BYTES>>>(
        xH, xL, WaH, WaL, b_attn, bQ, bK, nullptr, qkvH, qkvL, BT_, C3_, C_);

    // 2) flash attention (bf16 hi/lo out)
    attn_bf16<<<dim3(T_ / 128, NH_, B_), 256, ASMEM_BYTES>>>();

    // 3) proj (float out)
    gemm_bf16<1><<<dim3(C_ / 128, BT_ / 128), 256, GSMEM_BYTES>>>(
        yH, yL, WpH, WpL, b_proj, nullptr, nullptr, out, nullptr, nullptr, BT_, C_, C_);
}